// round 2
// baseline (speedup 1.0000x reference)
#include <cuda_runtime.h>
#include <math.h>
#include <float.h>

#define BB  2
#define SS  512
#define DD  256
#define HH  8
#define DKK 32
#define NKK 16

#define Z_ELEMS (BB*SS*NKK*DD)   // 4194304
#define Q_ELEMS (BB*HH*SS*SS)    // 4194304

// ---------------- scratch (static device allocations; no cudaMalloc) ----------------
__device__ float g_WT [7*65536];            // transposed weights [w][kk][d]
__device__ float g_q1 [BB*HH*SS*DKK];
__device__ float g_q1T[BB*HH*DKK*SS];
__device__ float g_v1 [BB*HH*SS*DKK];
__device__ float g_att1[BB*SS*DD];
__device__ float g_p  [BB*SS*DD];
__device__ float g_k4 [BB*HH*SS*DKK];
__device__ float g_k4T[BB*HH*DKK*SS];
__device__ float g_v4 [BB*HH*SS*DKK];
__device__ float g_qh [NKK*DD];
__device__ float g_r4 [BB*NKK*HH*SS];
__device__ float g_P4 [BB*NKK*HH*SS];
__device__ float g_out4[BB*NKK*SS*DD];

// ---------------- helpers ----------------
__device__ __forceinline__ float warpMax(float v){
#pragma unroll
    for (int o = 16; o; o >>= 1) v = fmaxf(v, __shfl_xor_sync(0xffffffffu, v, o));
    return v;
}
__device__ __forceinline__ float warpSum(float v){
#pragma unroll
    for (int o = 16; o; o >>= 1) v += __shfl_xor_sync(0xffffffffu, v, o);
    return v;
}
__device__ float blockMax(float v, float* s8, int tid){
    v = warpMax(v);
    if ((tid & 31) == 0) s8[tid >> 5] = v;
    __syncthreads();
    if (tid == 0){
        float m = s8[0];
#pragma unroll
        for (int w = 1; w < 8; w++) m = fmaxf(m, s8[w]);
        s8[0] = m;
    }
    __syncthreads();
    float r = s8[0];
    __syncthreads();
    return r;
}
__device__ float blockSum(float v, float* s8, int tid){
    v = warpSum(v);
    if ((tid & 31) == 0) s8[tid >> 5] = v;
    __syncthreads();
    if (tid == 0){
        float m = 0.f;
#pragma unroll
        for (int w = 0; w < 8; w++) m += s8[w];
        s8[0] = m;
    }
    __syncthreads();
    float r = s8[0];
    __syncthreads();
    return r;
}
// inclusive scan of 512 floats in smem, 256 threads (thread t owns 2t,2t+1)
__device__ void blockScan512(float* sdata, float* swarp, int tid){
    float a0 = sdata[2*tid], a1 = sdata[2*tid+1];
    float ts = a0 + a1;
    float v = ts;
#pragma unroll
    for (int o = 1; o < 32; o <<= 1){
        float n = __shfl_up_sync(0xffffffffu, v, o);
        if ((tid & 31) >= o) v += n;
    }
    if ((tid & 31) == 31) swarp[tid >> 5] = v;
    __syncthreads();
    if (tid < 8){
        float w = swarp[tid];
#pragma unroll
        for (int o = 1; o < 8; o <<= 1){
            float n = __shfl_up_sync(0xffu, w, o);
            if (tid >= o) w += n;
        }
        swarp[tid] = w;
    }
    __syncthreads();
    float base = (tid >= 32) ? swarp[(tid >> 5) - 1] : 0.f;
    float excl = base + (v - ts);
    sdata[2*tid]   = excl + a0;
    sdata[2*tid+1] = excl + a0 + a1;
    __syncthreads();
}

// ---------------- weight transpose:  g_WT[w][kk][d] = W[d][kk] ----------------
__global__ void __launch_bounds__(256) transpose_w_kernel(
        const float* Wq1, const float* Wv1, const float* Wo1,
        const float* Wq4, const float* Wk4, const float* Wv4, const float* Wo4){
    int idx = blockIdx.x * 256 + threadIdx.x;   // 7*65536 total
    int w = idx >> 16, e = idx & 65535;
    int d = e >> 8, kk = e & 255;
    const float* src;
    switch (w){
        case 0: src = Wq1; break;  case 1: src = Wv1; break;
        case 2: src = Wo1; break;  case 3: src = Wq4; break;
        case 4: src = Wk4; break;  case 5: src = Wv4; break;
        default: src = Wo4; break;
    }
    g_WT[w*65536 + kk*256 + d] = src[d*256 + kk];
}

// ---------------- projection GEMM: Y = X @ W^T + b, write heads layout (+optional T) ----
// grid.x * 32 rows, 256 threads. outsel: 0=q1(+T) 1=v1 2=k4(+T) 3=v4. xsel: 1 -> X=g_p
__global__ void __launch_bounds__(256) proj_kernel(
        const float* Xin, const float* bias, int wsel, int outsel, int xsel){
    __shared__ float xs[32][256];
    int tid = threadIdx.x;
    int row0 = blockIdx.x * 32;
    const float* X = (xsel == 1) ? g_p : Xin;
    for (int idx = tid; idx < 32*256; idx += 256)
        xs[idx >> 8][idx & 255] = X[(row0 + (idx >> 8))*256 + (idx & 255)];
    __syncthreads();

    int c = tid & 63, rg = tid >> 6;          // 4 cols, 8 rows each
    float4 acc[8];
#pragma unroll
    for (int r = 0; r < 8; r++) acc[r] = make_float4(0.f,0.f,0.f,0.f);
    const float4* WT4 = (const float4*)(g_WT + (size_t)wsel*65536);
#pragma unroll 4
    for (int kk = 0; kk < 256; kk++){
        float4 w = WT4[kk*64 + c];
#pragma unroll
        for (int r = 0; r < 8; r++){
            float x = xs[rg*8 + r][kk];
            acc[r].x += x*w.x; acc[r].y += x*w.y; acc[r].z += x*w.z; acc[r].w += x*w.w;
        }
    }
    float4 bb = ((const float4*)bias)[c];
    int col = c*4, h = col >> 5, dk = col & 31;
    float* Yh; float* YT = nullptr;
    switch (outsel){
        case 0: Yh = g_q1; YT = g_q1T; break;
        case 1: Yh = g_v1; break;
        case 2: Yh = g_k4; YT = g_k4T; break;
        default: Yh = g_v4; break;
    }
#pragma unroll
    for (int r = 0; r < 8; r++){
        int row = row0 + rg*8 + r;
        int bidx = row >> 9, s = row & 511;
        float4 v = make_float4(acc[r].x + bb.x, acc[r].y + bb.y,
                               acc[r].z + bb.z, acc[r].w + bb.w);
        ((float4*)Yh)[(((size_t)(bidx*HH + h)*SS + s)*DKK + dk) >> 2] = v;
        if (YT){
            size_t tb = (size_t)(bidx*HH + h)*DKK;
            YT[(tb + dk + 0)*SS + s] = v.x;
            YT[(tb + dk + 1)*SS + s] = v.y;
            YT[(tb + dk + 2)*SS + s] = v.z;
            YT[(tb + dk + 3)*SS + s] = v.w;
        }
    }
}

// ---------------- epilogue GEMM + residual + LayerNorm ----------------
// mode 0: X=g_att1, resid=q_emb rowwise, dst=g_p plain.  (32 blocks)
// mode 1: X=g_out4, resid=know_params[k], dst=z scatter. (512 blocks)
__global__ void __launch_bounds__(256) epi_kernel(
        const float* resid, const float* lng, const float* lnb,
        int wsel, const float* bias, int mode, float* dst){
    __shared__ float xs[32][256];
    int tid = threadIdx.x;
    int row0 = blockIdx.x * 32;
    const float* X = (mode == 0) ? g_att1 : g_out4;
    for (int idx = tid; idx < 32*256; idx += 256)
        xs[idx >> 8][idx & 255] = X[(row0 + (idx >> 8))*256 + (idx & 255)];
    __syncthreads();

    int c = tid & 63, rg = tid >> 6;
    float4 acc[8];
#pragma unroll
    for (int r = 0; r < 8; r++) acc[r] = make_float4(0.f,0.f,0.f,0.f);
    const float4* WT4 = (const float4*)(g_WT + (size_t)wsel*65536);
#pragma unroll 4
    for (int kk = 0; kk < 256; kk++){
        float4 w = WT4[kk*64 + c];
#pragma unroll
        for (int r = 0; r < 8; r++){
            float x = xs[rg*8 + r][kk];
            acc[r].x += x*w.x; acc[r].y += x*w.y; acc[r].z += x*w.z; acc[r].w += x*w.w;
        }
    }
    __syncthreads();   // all xs reads done; reuse as y buffer
    float4 bb = ((const float4*)bias)[c];
    int col = c*4;
#pragma unroll
    for (int r = 0; r < 8; r++){
        int row = row0 + rg*8 + r;
        float4 rs;
        if (mode == 0) rs = ((const float4*)resid)[row*64 + c];
        else { int k = (row >> 9) & 15; rs = ((const float4*)resid)[k*64 + c]; }
        xs[rg*8 + r][col + 0] = acc[r].x + bb.x + rs.x;
        xs[rg*8 + r][col + 1] = acc[r].y + bb.y + rs.y;
        xs[rg*8 + r][col + 2] = acc[r].z + bb.z + rs.z;
        xs[rg*8 + r][col + 3] = acc[r].w + bb.w + rs.w;
    }
    __syncthreads();

    int w = tid >> 5, lane = tid & 31;
#pragma unroll
    for (int rr = 0; rr < 4; rr++){
        int r = w*4 + rr, row = row0 + r;
        float sum = 0.f;
        for (int d = lane; d < 256; d += 32) sum += xs[r][d];
        sum = warpSum(sum);
        float mean = sum * (1.f/256.f);
        float vs = 0.f;
        for (int d = lane; d < 256; d += 32){ float t = xs[r][d] - mean; vs += t*t; }
        vs = warpSum(vs);
        float inv = rsqrtf(vs*(1.f/256.f) + 1e-5f);
        size_t base;
        float* out;
        if (mode == 0){ base = (size_t)row*256; out = g_p; }
        else {
            int b = row >> 13, k = (row >> 9) & 15, s = row & 511;
            base = ((size_t)(b*512 + s)*16 + k)*256; out = dst;
        }
        for (int d = lane; d < 256; d += 32)
            out[base + d] = (xs[r][d] - mean)*inv*lng[d] + lnb[d];
    }
}

// ---------------- knowledge-query projection: qh[k][d] ----------------
__global__ void __launch_bounds__(256) knowproj_kernel(const float* kp, const float* bq){
    __shared__ float kps[NKK*DD];
    int tid = threadIdx.x;
    for (int idx = tid; idx < NKK*DD; idx += 256) kps[idx] = kp[idx];
    __syncthreads();
    const float* WT = g_WT + 3*65536;   // Wq4^T
    float acc[NKK];
#pragma unroll
    for (int k = 0; k < NKK; k++) acc[k] = bq[tid];
    for (int kk = 0; kk < DD; kk++){
        float w = WT[kk*256 + tid];
#pragma unroll
        for (int k = 0; k < NKK; k++) acc[k] += kps[k*DD + kk]*w;
    }
#pragma unroll
    for (int k = 0; k < NKK; k++) g_qh[k*DD + tid] = acc[k];
}

// ---------------- block-4 score rows + exp prefix sums (one per (b,k,h)) ----------------
__global__ void __launch_bounds__(256) r4pre_kernel(){
    int idx = blockIdx.x;                 // (b*16+k)*8+h
    int h = idx & 7, bk = idx >> 3, b = bk >> 4, k = bk & 15;
    int tid = threadIdx.x;
    __shared__ float qv[DKK];
    __shared__ float sbuf[512];
    __shared__ float sred[8];
    if (tid < DKK) qv[tid] = g_qh[k*DD + h*DKK + tid];
    __syncthreads();
    const float* kT = g_k4T + (size_t)(b*HH + h)*DKK*SS;
    int j0 = tid, j1 = tid + 256;
    float r0 = 0.f, r1 = 0.f;
#pragma unroll
    for (int d = 0; d < DKK; d++){
        float q = qv[d];
        r0 += q*kT[d*SS + j0];
        r1 += q*kT[d*SS + j1];
    }
    const float sc = 0.17677669529663687f;  // 1/sqrt(32)
    r0 *= sc; r1 *= sc;
    size_t rb = (size_t)idx*SS;
    g_r4[rb + j0] = r0; g_r4[rb + j1] = r1;
    float M = blockMax(fmaxf(r0, r1), sred, tid);
    sbuf[j0] = expf(r0 - M); sbuf[j1] = expf(r1 - M);
    __syncthreads();
    blockScan512(sbuf, sred, tid);
    g_P4[rb + j0] = sbuf[j0]; g_P4[rb + j1] = sbuf[j1];
}

// ---------------- block-1 attention row kernel ----------------
__global__ void __launch_bounds__(256) attn1_kernel(const float* gam, float* qsc){
    int i = blockIdx.x, h = blockIdx.y, b = blockIdx.z;
    int tid = threadIdx.x;
    __shared__ float qv[DKK];
    __shared__ float sbuf[512];
    __shared__ float sred[8];
    __shared__ float pvred[8*32];
    int bh = b*HH + h;
    if (tid < DKK) qv[tid] = g_q1[((size_t)bh*SS + i)*DKK + tid];
    __syncthreads();
    const float* kT = g_q1T + (size_t)bh*DKK*SS;   // kq_same
    int j0 = tid, j1 = tid + 256;
    bool v0 = (j0 <= i), v1b = (j1 <= i);
    float r0 = 0.f, r1 = 0.f;
    if (v0){
#pragma unroll
        for (int d = 0; d < DKK; d++) r0 += qv[d]*kT[d*SS + j0];
    }
    if (v1b){
#pragma unroll
        for (int d = 0; d < DKK; d++) r1 += qv[d]*kT[d*SS + j1];
    }
    const float sc = 0.17677669529663687f;
    r0 *= sc; r1 *= sc;
    float m1 = blockMax(fmaxf(v0 ? r0 : -FLT_MAX, v1b ? r1 : -FLT_MAX), sred, tid);
    float e0 = v0  ? expf(r0 - m1) : 0.f;
    float e1 = v1b ? expf(r1 - m1) : 0.f;
    sbuf[j0] = e0; sbuf[j1] = e1;
    __syncthreads();
    blockScan512(sbuf, sred, tid);            // inclusive prefix of exp
    float Z = sbuf[i], invZ = 1.f / Z;
    float PE0 = sbuf[j0], PE1 = sbuf[j1];
    float g = fabsf(gam[h]);
    float s20 = -FLT_MAX, s21 = -FLT_MAX;
    if (v0){
        float tail = fmaxf((Z - PE0)*invZ, 0.f);
        float u = tail * (float)(i - j0);
        float eff = fminf(fmaxf(expf(-g*sqrtf(fmaxf(u, 0.f))), 1e-5f), 1e5f);
        s20 = r0*eff;
    }
    if (v1b){
        float tail = fmaxf((Z - PE1)*invZ, 0.f);
        float u = tail * (float)(i - j1);
        float eff = fminf(fmaxf(expf(-g*sqrtf(fmaxf(u, 0.f))), 1e-5f), 1e5f);
        s21 = r1*eff;
    }
    float m2 = blockMax(fmaxf(s20, s21), sred, tid);
    float f0 = v0  ? expf(s20 - m2) : 0.f;
    float f1 = v1b ? expf(s21 - m2) : 0.f;
    float Z2 = blockSum(f0 + f1, sred, tid);
    float invZ2 = 1.f / Z2;
    float p0 = f0*invZ2, p1 = f1*invZ2;
    size_t qrow = ((size_t)bh*SS + i)*SS;
    qsc[qrow + j0] = p0;
    qsc[qrow + j1] = p1;
    sbuf[j0] = p0; sbuf[j1] = p1;
    __syncthreads();
    int d = tid & 31, grp = tid >> 5;
    const float* vrow = g_v1 + (size_t)bh*SS*DKK;
    float acc = 0.f;
    for (int j = grp; j <= i; j += 8) acc += sbuf[j]*vrow[j*DKK + d];
    pvred[grp*32 + d] = acc;
    __syncthreads();
    if (tid < 32){
        float a = 0.f;
#pragma unroll
        for (int g2 = 0; g2 < 8; g2++) a += pvred[g2*32 + tid];
        g_att1[((size_t)b*SS + i)*DD + h*DKK + tid] = a;
    }
}

// ---------------- block-4 attention row kernel ----------------
__global__ void __launch_bounds__(256) attn4_kernel(const float* gam, float* ksc){
    int i = blockIdx.x, h = blockIdx.y, z = blockIdx.z;
    int b = z >> 4, k = z & 15;
    int tid = threadIdx.x;
    __shared__ float sbuf[512];
    __shared__ float sred[8];
    __shared__ float pvred[8*32];
    size_t krow = (((size_t)(b*HH + h)*SS + i)*NKK + k)*SS;
    size_t orow = ((size_t)(b*NKK + k)*SS + i)*DD + h*DKK;
    if (i == 0){                                   // fully masked row
        for (int j = tid; j < SS; j += 256) ksc[krow + j] = 0.f;
        if (tid < DKK) g_out4[orow + tid] = 0.f;
        return;
    }
    size_t rb = ((size_t)z*HH + h)*SS;             // (b,k,h) score-row base
    float S1 = g_P4[rb + i - 1];
    float invS1 = 1.f / S1;
    float g = fabsf(gam[h]);
    int j0 = tid, j1 = tid + 256;
    bool val0 = (j0 < i), val1 = (j1 < i);
    float s20 = -FLT_MAX, s21 = -FLT_MAX;
    if (val0){
        float r = g_r4[rb + j0];
        float tail = fmaxf((S1 - g_P4[rb + j0])*invS1, 0.f);
        float u = tail * (float)(i - j0);
        float eff = fminf(fmaxf(expf(-g*sqrtf(fmaxf(u, 0.f))), 1e-5f), 1e5f);
        s20 = r*eff;
    }
    if (val1){
        float r = g_r4[rb + j1];
        float tail = fmaxf((S1 - g_P4[rb + j1])*invS1, 0.f);
        float u = tail * (float)(i - j1);
        float eff = fminf(fmaxf(expf(-g*sqrtf(fmaxf(u, 0.f))), 1e-5f), 1e5f);
        s21 = r*eff;
    }
    float m2 = blockMax(fmaxf(s20, s21), sred, tid);
    float e0 = val0 ? expf(s20 - m2) : 0.f;
    float e1 = val1 ? expf(s21 - m2) : 0.f;
    float Z = blockSum(e0 + e1, sred, tid);
    float scmax = fminf(Z, 5.f) / Z;               // maxout: min(1/pmax,5)/Z, pmax=1/Z
    float p0 = e0*scmax, p1 = e1*scmax;
    ksc[krow + j0] = p0;
    ksc[krow + j1] = p1;
    sbuf[j0] = p0; sbuf[j1] = p1;
    __syncthreads();
    int d = tid & 31, grp = tid >> 5;
    const float* vrow = g_v4 + (size_t)(b*HH + h)*SS*DKK;
    float acc = 0.f;
    for (int j = grp; j < i; j += 8) acc += sbuf[j]*vrow[j*DKK + d];
    pvred[grp*32 + d] = acc;
    __syncthreads();
    if (tid < 32){
        float a = 0.f;
#pragma unroll
        for (int g2 = 0; g2 < 8; g2++) a += pvred[g2*32 + tid];
        g_out4[orow + tid] = a;
    }
}

// ---------------- launch ----------------
extern "C" void kernel_launch(void* const* d_in, const int* in_sizes, int n_in,
                              void* d_out, int out_size){
    (void)in_sizes; (void)n_in; (void)out_size;
    const float* q_emb = (const float*)d_in[0];
    const float* s_emb = (const float*)d_in[1];
    // d_in[2]=s_emb_extr, d_in[3]=lens, d_in[4]=at  -- unused by reference
    const float* Wq1 = (const float*)d_in[5];
    const float* bq1 = (const float*)d_in[6];
    const float* Wv1 = (const float*)d_in[7];
    const float* bv1 = (const float*)d_in[8];
    const float* Wo1 = (const float*)d_in[9];
    const float* bo1 = (const float*)d_in[10];
    const float* gam1= (const float*)d_in[11];
    const float* ln1g= (const float*)d_in[12];
    const float* ln1b= (const float*)d_in[13];
    const float* Wq4 = (const float*)d_in[14];
    const float* bq4 = (const float*)d_in[15];
    const float* Wk4 = (const float*)d_in[16];
    const float* bk4 = (const float*)d_in[17];
    const float* Wv4 = (const float*)d_in[18];
    const float* bv4 = (const float*)d_in[19];
    const float* Wo4 = (const float*)d_in[20];
    const float* bo4 = (const float*)d_in[21];
    const float* gam4= (const float*)d_in[22];
    const float* ln4g= (const float*)d_in[23];
    const float* ln4b= (const float*)d_in[24];
    const float* knowp=(const float*)d_in[25];

    float* out  = (float*)d_out;
    float* z_out = out;                       // [B,S,NK*D]
    float* q_out = out + Z_ELEMS;             // [B,H,S,S]
    float* k_out = out + Z_ELEMS + Q_ELEMS;   // [B,H,S,NK,S]

    transpose_w_kernel<<<1792, 256>>>(Wq1, Wv1, Wo1, Wq4, Wk4, Wv4, Wo4);
    // block 1
    proj_kernel<<<32, 256>>>(q_emb, bq1, 0, 0, 0);        // q1 (+T); k1 == q1
    proj_kernel<<<32, 256>>>(s_emb, bv1, 1, 1, 0);        // v1
    attn1_kernel<<<dim3(SS, HH, BB), 256>>>(gam1, q_out);
    epi_kernel<<<32, 256>>>(q_emb, ln1g, ln1b, 2, bo1, 0, nullptr);   // -> g_p
    // block 4
    proj_kernel<<<32, 256>>>(q_emb, bk4, 4, 2, 0);        // k4 (+T)
    proj_kernel<<<32, 256>>>(q_emb /*ignored*/, bv4, 5, 3, 1);  // v4 from g_p
    knowproj_kernel<<<1, 256>>>(knowp, bq4);
    r4pre_kernel<<<256, 256>>>();
    attn4_kernel<<<dim3(SS, HH, BB*NKK), 256>>>(gam4, k_out);
    epi_kernel<<<512, 256>>>(knowp, ln4g, ln4b, 6, bo4, 1, z_out);    // -> z
}

// round 3
// speedup vs baseline: 1.0818x; 1.0818x over previous
#include <cuda_runtime.h>
#include <math.h>
#include <float.h>

#define BB  2
#define SS  512
#define DD  256
#define HH  8
#define DKK 32
#define NKK 16
#define TI  128

#define Z_ELEMS (BB*SS*NKK*DD)   // 4194304
#define Q_ELEMS (BB*HH*SS*SS)    // 4194304

typedef unsigned long long ull;

// ---------------- f32x2 packed-math helpers ----------------
__device__ __forceinline__ ull ffma2(ull a, ull b, ull c){
    ull d;
    asm("fma.rn.f32x2 %0, %1, %2, %3;" : "=l"(d) : "l"(a), "l"(b), "l"(c));
    return d;
}
__device__ __forceinline__ ull pack2(float lo, float hi){
    ull d;
    asm("mov.b64 %0, {%1, %2};" : "=l"(d) : "f"(lo), "f"(hi));
    return d;
}
__device__ __forceinline__ void unpack2(ull v, float& lo, float& hi){
    asm("mov.b64 {%0, %1}, %2;" : "=f"(lo), "=f"(hi) : "l"(v));
}

// ---------------- scratch (static device allocations; no cudaMalloc) ----------------
__device__ float g_WT [7*65536];            // transposed weights [w][kk][d]
__device__ float g_q1 [BB*HH*SS*DKK];
__device__ float g_q1T[BB*HH*DKK*SS];
__device__ float g_v1 [BB*HH*SS*DKK];
__device__ float g_att1[BB*SS*DD];
__device__ float g_p  [BB*SS*DD];
__device__ float g_k4 [BB*HH*SS*DKK];
__device__ float g_k4T[BB*HH*DKK*SS];
__device__ float g_v4 [BB*HH*SS*DKK];
__device__ float g_qh [NKK*DD];
__device__ float g_r4 [BB*NKK*HH*SS];
__device__ float g_P4 [BB*NKK*HH*SS];
__device__ float g_out4[BB*NKK*SS*DD];

// ---------------- helpers ----------------
__device__ __forceinline__ float warpMax(float v){
#pragma unroll
    for (int o = 16; o; o >>= 1) v = fmaxf(v, __shfl_xor_sync(0xffffffffu, v, o));
    return v;
}
__device__ __forceinline__ float warpSum(float v){
#pragma unroll
    for (int o = 16; o; o >>= 1) v += __shfl_xor_sync(0xffffffffu, v, o);
    return v;
}
__device__ float blockMax(float v, float* s8, int tid){
    v = warpMax(v);
    if ((tid & 31) == 0) s8[tid >> 5] = v;
    __syncthreads();
    if (tid == 0){
        float m = s8[0];
#pragma unroll
        for (int w = 1; w < 8; w++) m = fmaxf(m, s8[w]);
        s8[0] = m;
    }
    __syncthreads();
    float r = s8[0];
    __syncthreads();
    return r;
}
__device__ float blockSum(float v, float* s8, int tid){
    v = warpSum(v);
    if ((tid & 31) == 0) s8[tid >> 5] = v;
    __syncthreads();
    if (tid == 0){
        float m = 0.f;
#pragma unroll
        for (int w = 0; w < 8; w++) m += s8[w];
        s8[0] = m;
    }
    __syncthreads();
    float r = s8[0];
    __syncthreads();
    return r;
}
// inclusive scan of 512 floats in smem, 256 threads (thread t owns 2t,2t+1)
__device__ void blockScan512(float* sdata, float* swarp, int tid){
    float a0 = sdata[2*tid], a1 = sdata[2*tid+1];
    float ts = a0 + a1;
    float v = ts;
#pragma unroll
    for (int o = 1; o < 32; o <<= 1){
        float n = __shfl_up_sync(0xffffffffu, v, o);
        if ((tid & 31) >= o) v += n;
    }
    if ((tid & 31) == 31) swarp[tid >> 5] = v;
    __syncthreads();
    if (tid < 8){
        float w = swarp[tid];
#pragma unroll
        for (int o = 1; o < 8; o <<= 1){
            float n = __shfl_up_sync(0xffu, w, o);
            if (tid >= o) w += n;
        }
        swarp[tid] = w;
    }
    __syncthreads();
    float base = (tid >= 32) ? swarp[(tid >> 5) - 1] : 0.f;
    float excl = base + (v - ts);
    sdata[2*tid]   = excl + a0;
    sdata[2*tid+1] = excl + a0 + a1;
    __syncthreads();
}

// ---------------- weight transpose:  g_WT[w][kk][d] = W[d][kk] ----------------
__global__ void __launch_bounds__(256) transpose_w_kernel(
        const float* Wq1, const float* Wv1, const float* Wo1,
        const float* Wq4, const float* Wk4, const float* Wv4, const float* Wo4){
    int idx = blockIdx.x * 256 + threadIdx.x;   // 7*65536 total
    int w = idx >> 16, e = idx & 65535;
    int d = e >> 8, kk = e & 255;
    const float* src;
    switch (w){
        case 0: src = Wq1; break;  case 1: src = Wv1; break;
        case 2: src = Wo1; break;  case 3: src = Wq4; break;
        case 4: src = Wk4; break;  case 5: src = Wv4; break;
        default: src = Wo4; break;
    }
    g_WT[w*65536 + kk*256 + d] = src[d*256 + kk];
}

// ---------------- projection GEMM: Y = X @ W^T + b, write heads layout (+optional T) ----
// grid.x * 32 rows, 256 threads. outsel: 0=q1(+T) 1=v1 2=k4(+T) 3=v4. xsel: 1 -> X=g_p
__global__ void __launch_bounds__(256) proj_kernel(
        const float* Xin, const float* bias, int wsel, int outsel, int xsel){
    __shared__ float xs[32][256];
    int tid = threadIdx.x;
    int row0 = blockIdx.x * 32;
    const float* X = (xsel == 1) ? g_p : Xin;
    for (int idx = tid; idx < 32*256; idx += 256)
        xs[idx >> 8][idx & 255] = X[(row0 + (idx >> 8))*256 + (idx & 255)];
    __syncthreads();

    int c = tid & 63, rg = tid >> 6;          // 4 cols, 8 rows each
    ull acc2[8][2];
#pragma unroll
    for (int r = 0; r < 8; r++){ acc2[r][0] = 0ull; acc2[r][1] = 0ull; }
    const ulonglong2* WT2 = (const ulonglong2*)(g_WT + (size_t)wsel*65536);
#pragma unroll 4
    for (int kk = 0; kk < 256; kk++){
        ulonglong2 wv = WT2[kk*64 + c];
#pragma unroll
        for (int r = 0; r < 8; r++){
            float x = xs[rg*8 + r][kk];
            ull xx = pack2(x, x);
            acc2[r][0] = ffma2(xx, wv.x, acc2[r][0]);
            acc2[r][1] = ffma2(xx, wv.y, acc2[r][1]);
        }
    }
    float4 bb = ((const float4*)bias)[c];
    int col = c*4, h = col >> 5, dk = col & 31;
    float* Yh; float* YT = nullptr;
    switch (outsel){
        case 0: Yh = g_q1; YT = g_q1T; break;
        case 1: Yh = g_v1; break;
        case 2: Yh = g_k4; YT = g_k4T; break;
        default: Yh = g_v4; break;
    }
#pragma unroll
    for (int r = 0; r < 8; r++){
        int row = row0 + rg*8 + r;
        int bidx = row >> 9, s = row & 511;
        float a0,a1,a2,a3;
        unpack2(acc2[r][0], a0, a1);
        unpack2(acc2[r][1], a2, a3);
        float4 v = make_float4(a0 + bb.x, a1 + bb.y, a2 + bb.z, a3 + bb.w);
        ((float4*)Yh)[(((size_t)(bidx*HH + h)*SS + s)*DKK + dk) >> 2] = v;
        if (YT){
            size_t tb = (size_t)(bidx*HH + h)*DKK;
            YT[(tb + dk + 0)*SS + s] = v.x;
            YT[(tb + dk + 1)*SS + s] = v.y;
            YT[(tb + dk + 2)*SS + s] = v.z;
            YT[(tb + dk + 3)*SS + s] = v.w;
        }
    }
}

// ---------------- epilogue GEMM + residual + LayerNorm ----------------
// mode 0: X=g_att1, resid=q_emb rowwise, dst=g_p plain.  (32 blocks)
// mode 1: X=g_out4, resid=know_params[k], dst=z scatter. (512 blocks)
__global__ void __launch_bounds__(256) epi_kernel(
        const float* resid, const float* lng, const float* lnb,
        int wsel, const float* bias, int mode, float* dst){
    __shared__ float xs[32][256];
    int tid = threadIdx.x;
    int row0 = blockIdx.x * 32;
    const float* X = (mode == 0) ? g_att1 : g_out4;
    for (int idx = tid; idx < 32*256; idx += 256)
        xs[idx >> 8][idx & 255] = X[(row0 + (idx >> 8))*256 + (idx & 255)];
    __syncthreads();

    int c = tid & 63, rg = tid >> 6;
    ull acc2[8][2];
#pragma unroll
    for (int r = 0; r < 8; r++){ acc2[r][0] = 0ull; acc2[r][1] = 0ull; }
    const ulonglong2* WT2 = (const ulonglong2*)(g_WT + (size_t)wsel*65536);
#pragma unroll 4
    for (int kk = 0; kk < 256; kk++){
        ulonglong2 wv = WT2[kk*64 + c];
#pragma unroll
        for (int r = 0; r < 8; r++){
            float x = xs[rg*8 + r][kk];
            ull xx = pack2(x, x);
            acc2[r][0] = ffma2(xx, wv.x, acc2[r][0]);
            acc2[r][1] = ffma2(xx, wv.y, acc2[r][1]);
        }
    }
    __syncthreads();   // all xs reads done; reuse as y buffer
    float4 bb = ((const float4*)bias)[c];
    int col = c*4;
#pragma unroll
    for (int r = 0; r < 8; r++){
        int row = row0 + rg*8 + r;
        float4 rs;
        if (mode == 0) rs = ((const float4*)resid)[row*64 + c];
        else { int k = (row >> 9) & 15; rs = ((const float4*)resid)[k*64 + c]; }
        float a0,a1,a2,a3;
        unpack2(acc2[r][0], a0, a1);
        unpack2(acc2[r][1], a2, a3);
        xs[rg*8 + r][col + 0] = a0 + bb.x + rs.x;
        xs[rg*8 + r][col + 1] = a1 + bb.y + rs.y;
        xs[rg*8 + r][col + 2] = a2 + bb.z + rs.z;
        xs[rg*8 + r][col + 3] = a3 + bb.w + rs.w;
    }
    __syncthreads();

    int w = tid >> 5, lane = tid & 31;
#pragma unroll
    for (int rr = 0; rr < 4; rr++){
        int r = w*4 + rr, row = row0 + r;
        float sum = 0.f;
        for (int d = lane; d < 256; d += 32) sum += xs[r][d];
        sum = warpSum(sum);
        float mean = sum * (1.f/256.f);
        float vs = 0.f;
        for (int d = lane; d < 256; d += 32){ float t = xs[r][d] - mean; vs += t*t; }
        vs = warpSum(vs);
        float inv = rsqrtf(vs*(1.f/256.f) + 1e-5f);
        size_t base;
        float* out;
        if (mode == 0){ base = (size_t)row*256; out = g_p; }
        else {
            int b = row >> 13, k = (row >> 9) & 15, s = row & 511;
            base = ((size_t)(b*512 + s)*16 + k)*256; out = dst;
        }
        for (int d = lane; d < 256; d += 32)
            out[base + d] = (xs[r][d] - mean)*inv*lng[d] + lnb[d];
    }
}

// ---------------- knowledge-query projection: qh[k][d] ----------------
__global__ void __launch_bounds__(256) knowproj_kernel(const float* kp, const float* bq){
    __shared__ float kps[NKK*DD];
    int tid = threadIdx.x;
    for (int idx = tid; idx < NKK*DD; idx += 256) kps[idx] = kp[idx];
    __syncthreads();
    const float* WT = g_WT + 3*65536;   // Wq4^T
    float acc[NKK];
#pragma unroll
    for (int k = 0; k < NKK; k++) acc[k] = bq[tid];
    for (int kk = 0; kk < DD; kk++){
        float w = WT[kk*256 + tid];
#pragma unroll
        for (int k = 0; k < NKK; k++) acc[k] += kps[k*DD + kk]*w;
    }
#pragma unroll
    for (int k = 0; k < NKK; k++) g_qh[k*DD + tid] = acc[k];
}

// ---------------- block-4 score rows + exp prefix sums (one per (b,k,h)) ----------------
__global__ void __launch_bounds__(256) r4pre_kernel(){
    int idx = blockIdx.x;                 // (b*16+k)*8+h
    int h = idx & 7, bk = idx >> 3, b = bk >> 4, k = bk & 15;
    int tid = threadIdx.x;
    __shared__ float qv[DKK];
    __shared__ float sbuf[512];
    __shared__ float sred[8];
    if (tid < DKK) qv[tid] = g_qh[k*DD + h*DKK + tid];
    __syncthreads();
    const float* kT = g_k4T + (size_t)(b*HH + h)*DKK*SS;
    int j0 = tid, j1 = tid + 256;
    float r0 = 0.f, r1 = 0.f;
#pragma unroll
    for (int d = 0; d < DKK; d++){
        float q = qv[d];
        r0 += q*kT[d*SS + j0];
        r1 += q*kT[d*SS + j1];
    }
    const float sc = 0.17677669529663687f;  // 1/sqrt(32)
    r0 *= sc; r1 *= sc;
    size_t rb = (size_t)idx*SS;
    g_r4[rb + j0] = r0; g_r4[rb + j1] = r1;
    float M = blockMax(fmaxf(r0, r1), sred, tid);
    sbuf[j0] = expf(r0 - M); sbuf[j1] = expf(r1 - M);
    __syncthreads();
    blockScan512(sbuf, sred, tid);
    g_P4[rb + j0] = sbuf[j0]; g_P4[rb + j1] = sbuf[j1];
}

// ---------------- block-1 attention row kernel (unchanged) ----------------
__global__ void __launch_bounds__(256) attn1_kernel(const float* gam, float* qsc){
    int i = blockIdx.x, h = blockIdx.y, b = blockIdx.z;
    int tid = threadIdx.x;
    __shared__ float qv[DKK];
    __shared__ float sbuf[512];
    __shared__ float sred[8];
    __shared__ float pvred[8*32];
    int bh = b*HH + h;
    if (tid < DKK) qv[tid] = g_q1[((size_t)bh*SS + i)*DKK + tid];
    __syncthreads();
    const float* kT = g_q1T + (size_t)bh*DKK*SS;   // kq_same
    int j0 = tid, j1 = tid + 256;
    bool v0 = (j0 <= i), v1b = (j1 <= i);
    float r0 = 0.f, r1 = 0.f;
    if (v0){
#pragma unroll
        for (int d = 0; d < DKK; d++) r0 += qv[d]*kT[d*SS + j0];
    }
    if (v1b){
#pragma unroll
        for (int d = 0; d < DKK; d++) r1 += qv[d]*kT[d*SS + j1];
    }
    const float sc = 0.17677669529663687f;
    r0 *= sc; r1 *= sc;
    float m1 = blockMax(fmaxf(v0 ? r0 : -FLT_MAX, v1b ? r1 : -FLT_MAX), sred, tid);
    float e0 = v0  ? expf(r0 - m1) : 0.f;
    float e1 = v1b ? expf(r1 - m1) : 0.f;
    sbuf[j0] = e0; sbuf[j1] = e1;
    __syncthreads();
    blockScan512(sbuf, sred, tid);            // inclusive prefix of exp
    float Z = sbuf[i], invZ = 1.f / Z;
    float PE0 = sbuf[j0], PE1 = sbuf[j1];
    float g = fabsf(gam[h]);
    float s20 = -FLT_MAX, s21 = -FLT_MAX;
    if (v0){
        float tail = fmaxf((Z - PE0)*invZ, 0.f);
        float u = tail * (float)(i - j0);
        float eff = fminf(fmaxf(expf(-g*sqrtf(fmaxf(u, 0.f))), 1e-5f), 1e5f);
        s20 = r0*eff;
    }
    if (v1b){
        float tail = fmaxf((Z - PE1)*invZ, 0.f);
        float u = tail * (float)(i - j1);
        float eff = fminf(fmaxf(expf(-g*sqrtf(fmaxf(u, 0.f))), 1e-5f), 1e5f);
        s21 = r1*eff;
    }
    float m2 = blockMax(fmaxf(s20, s21), sred, tid);
    float f0 = v0  ? expf(s20 - m2) : 0.f;
    float f1 = v1b ? expf(s21 - m2) : 0.f;
    float Z2 = blockSum(f0 + f1, sred, tid);
    float invZ2 = 1.f / Z2;
    float p0 = f0*invZ2, p1 = f1*invZ2;
    size_t qrow = ((size_t)bh*SS + i)*SS;
    qsc[qrow + j0] = p0;
    qsc[qrow + j1] = p1;
    sbuf[j0] = p0; sbuf[j1] = p1;
    __syncthreads();
    int d = tid & 31, grp = tid >> 5;
    const float* vrow = g_v1 + (size_t)bh*SS*DKK;
    float acc = 0.f;
    for (int j = grp; j <= i; j += 8) acc += sbuf[j]*vrow[j*DKK + d];
    pvred[grp*32 + d] = acc;
    __syncthreads();
    if (tid < 32){
        float a = 0.f;
#pragma unroll
        for (int g2 = 0; g2 < 8; g2++) a += pvred[g2*32 + tid];
        g_att1[((size_t)b*SS + i)*DD + h*DKK + tid] = a;
    }
}

// ---------------- block-4 attention: tiled flash-style kernel ----------------
// grid: (4 i-tiles, NK, B*H). block 256.
// One block = (b,k,h) x 128 query rows. Score row r and prefix P shared across rows.
__global__ void __launch_bounds__(256) attn4_kernel(const float* gam, float* ksc){
    int tile = blockIdx.x;
    int k    = blockIdx.y;
    int bh   = blockIdx.z;          // b*8+h
    int b = bh >> 3, h = bh & 7;
    int tid = threadIdx.x;
    int lane = tid & 31, w = tid >> 5;
    int i0 = tile * TI;
    int Jlim = i0 + TI;             // == min(i0+TI, SS) since 4*128 = 512

    __shared__ float r_s[SS];
    __shared__ float P_s[SS];
    __shared__ float p_s[64][130];          // [j_in_chunk][row], padded
    __shared__ float m2_s[TI], sc_s[TI], is_s[TI];

    size_t rb = ((size_t)((b*NKK + k)*HH + h)) * SS;
    for (int j = tid; j < SS; j += 256){
        r_s[j] = g_r4[rb + j];
        P_s[j] = g_P4[rb + j];
    }
    __syncthreads();

    float g = fabsf(gam[h]);

    // ---- stats: warp-per-row, register-stashed scores ----
    for (int m = 0; m < TI/8; m++){
        int ii = w + 8*m;
        int i  = i0 + ii;
        float invS1 = (i > 0) ? 1.f / P_s[i-1] : 0.f;
        float s2v[16];
        float mx = -FLT_MAX;
#pragma unroll
        for (int c = 0; c < 16; c++){
            s2v[c] = -FLT_MAX;
            if (c*32 < i){
                int j = lane + 32*c;
                if (j < i){
                    float r = r_s[j];
                    float tail = fmaxf(1.f - P_s[j]*invS1, 0.f);
                    float u = tail * (float)(i - j);
                    float eff = fminf(fmaxf(__expf(-g*sqrtf(u)), 1e-5f), 1e5f);
                    float s2 = r*eff;
                    s2v[c] = s2;
                    mx = fmaxf(mx, s2);
                }
            }
        }
        float m2 = warpMax(mx);
        float Zp = 0.f;
#pragma unroll
        for (int c = 0; c < 16; c++)
            if (c*32 < i) Zp += __expf(s2v[c] - m2);
        float Z = warpSum(Zp);
        if (lane == 0){
            m2_s[ii] = m2;
            sc_s[ii] = (Z > 0.f) ? fminf(Z, 5.f)/Z : 0.f;
            is_s[ii] = invS1;
        }
    }
    __syncthreads();

    // k_scores base for row i0 of this (b,h,k); row stride = NKK*SS floats
    size_t kbase0 = (((size_t)(b*HH + h)*SS + i0)*NKK + k)*SS;

    // ---- zero-fill masked tail columns [Jlim, SS) ----
    if (Jlim < SS){
        for (int m = 0; m < TI/8; m++){
            int ii = w + 8*m;
            float4* dst = (float4*)(ksc + kbase0 + (size_t)ii*(NKK*SS));
            for (int j4 = (Jlim >> 2) + lane; j4 < (SS >> 2); j4 += 32)
                dst[j4] = make_float4(0.f, 0.f, 0.f, 0.f);
        }
    }

    // ---- chunked p-materialization + PV GEMM ----
    int d0  = (tid & 7) * 4;        // 8 lanesets cover d = 0..31
    int ii0 = (tid >> 3) * 4;       // 32 row-quads cover 128 rows
    ull acc2[2][4];
#pragma unroll
    for (int q = 0; q < 2; q++)
#pragma unroll
        for (int dc = 0; dc < 4; dc++) acc2[q][dc] = 0ull;
    const float* vbase = g_v4 + (size_t)bh*SS*DKK;
    int ilimT = i0 + ii0 + 4;       // chunks with jc >= ilimT contribute nothing to this thread

    for (int jc = 0; jc < Jlim; jc += 64){
        // phase A: compute p for 64 columns x 128 rows; warp-per-row, lanes = j
        for (int m = 0; m < TI/8; m++){
            int ii = w + 8*m;
            int i  = i0 + ii;
            float m2 = m2_s[ii], sc = sc_s[ii], invS1 = is_s[ii];
            float* krow = ksc + kbase0 + (size_t)ii*(NKK*SS);
#pragma unroll
            for (int q = 0; q < 2; q++){
                int j = jc + lane + 32*q;
                float p = 0.f;
                if (j < i){
                    float r = r_s[j];
                    float tail = fmaxf(1.f - P_s[j]*invS1, 0.f);
                    float u = tail * (float)(i - j);
                    float eff = fminf(fmaxf(__expf(-g*sqrtf(u)), 1e-5f), 1e5f);
                    p = __expf(r*eff - m2) * sc;
                }
                p_s[j - jc][ii] = p;
                krow[j] = p;
            }
        }
        __syncthreads();
        // phase B: register-tiled PV accumulate over this chunk
        if (jc < ilimT){
#pragma unroll 2
            for (int jj = 0; jj < 64; jj++){
                float4 v = *(const float4*)(vbase + (size_t)(jc + jj)*DKK + d0);
                ull vx = pack2(v.x, v.x), vy = pack2(v.y, v.y);
                ull vz = pack2(v.z, v.z), vw = pack2(v.w, v.w);
#pragma unroll
                for (int q = 0; q < 2; q++){
                    ull pp = *(const ull*)&p_s[jj][ii0 + 2*q];   // {p[ii0+2q], p[ii0+2q+1]}
                    acc2[q][0] = ffma2(pp, vx, acc2[q][0]);
                    acc2[q][1] = ffma2(pp, vy, acc2[q][1]);
                    acc2[q][2] = ffma2(pp, vz, acc2[q][2]);
                    acc2[q][3] = ffma2(pp, vw, acc2[q][3]);
                }
            }
        }
        __syncthreads();
    }

    // ---- store out4 ----
    float va[4][4];
#pragma unroll
    for (int q = 0; q < 2; q++)
#pragma unroll
        for (int dc = 0; dc < 4; dc++)
            unpack2(acc2[q][dc], va[2*q][dc], va[2*q+1][dc]);
    float* obase = g_out4 + ((size_t)(b*NKK + k)*SS)*DD + h*DKK;
#pragma unroll
    for (int r = 0; r < 4; r++){
        *(float4*)(obase + (size_t)(i0 + ii0 + r)*DD + d0) =
            make_float4(va[r][0], va[r][1], va[r][2], va[r][3]);
    }
}

// ---------------- launch ----------------
extern "C" void kernel_launch(void* const* d_in, const int* in_sizes, int n_in,
                              void* d_out, int out_size){
    (void)in_sizes; (void)n_in; (void)out_size;
    const float* q_emb = (const float*)d_in[0];
    const float* s_emb = (const float*)d_in[1];
    // d_in[2]=s_emb_extr, d_in[3]=lens, d_in[4]=at  -- unused by reference
    const float* Wq1 = (const float*)d_in[5];
    const float* bq1 = (const float*)d_in[6];
    const float* Wv1 = (const float*)d_in[7];
    const float* bv1 = (const float*)d_in[8];
    const float* Wo1 = (const float*)d_in[9];
    const float* bo1 = (const float*)d_in[10];
    const float* gam1= (const float*)d_in[11];
    const float* ln1g= (const float*)d_in[12];
    const float* ln1b= (const float*)d_in[13];
    const float* Wq4 = (const float*)d_in[14];
    const float* bq4 = (const float*)d_in[15];
    const float* Wk4 = (const float*)d_in[16];
    const float* bk4 = (const float*)d_in[17];
    const float* Wv4 = (const float*)d_in[18];
    const float* bv4 = (const float*)d_in[19];
    const float* Wo4 = (const float*)d_in[20];
    const float* bo4 = (const float*)d_in[21];
    const float* gam4= (const float*)d_in[22];
    const float* ln4g= (const float*)d_in[23];
    const float* ln4b= (const float*)d_in[24];
    const float* knowp=(const float*)d_in[25];

    float* out  = (float*)d_out;
    float* z_out = out;                       // [B,S,NK*D]
    float* q_out = out + Z_ELEMS;             // [B,H,S,S]
    float* k_out = out + Z_ELEMS + Q_ELEMS;   // [B,H,S,NK,S]

    transpose_w_kernel<<<1792, 256>>>(Wq1, Wv1, Wo1, Wq4, Wk4, Wv4, Wo4);
    // block 1
    proj_kernel<<<32, 256>>>(q_emb, bq1, 0, 0, 0);        // q1 (+T); k1 == q1
    proj_kernel<<<32, 256>>>(s_emb, bv1, 1, 1, 0);        // v1
    attn1_kernel<<<dim3(SS, HH, BB), 256>>>(gam1, q_out);
    epi_kernel<<<32, 256>>>(q_emb, ln1g, ln1b, 2, bo1, 0, nullptr);   // -> g_p
    // block 4
    proj_kernel<<<32, 256>>>(q_emb, bk4, 4, 2, 0);        // k4 (+T)
    proj_kernel<<<32, 256>>>(q_emb /*ignored*/, bv4, 5, 3, 1);  // v4 from g_p
    knowproj_kernel<<<1, 256>>>(knowp, bq4);
    r4pre_kernel<<<256, 256>>>();
    attn4_kernel<<<dim3(4, NKK, BB*HH), 256>>>(gam4, k_out);
    epi_kernel<<<512, 256>>>(knowp, ln4g, ln4b, 6, bo4, 1, z_out);    // -> z
}

// round 4
// speedup vs baseline: 1.7580x; 1.6250x over previous
#include <cuda_runtime.h>
#include <math.h>
#include <float.h>

#define BB  2
#define SS  512
#define DD  256
#define HH  8
#define DKK 32
#define NKK 16
#define TI  128

#define Z_ELEMS (BB*SS*NKK*DD)   // 4194304
#define Q_ELEMS (BB*HH*SS*SS)    // 4194304

typedef unsigned long long ull;

// ---------------- f32x2 packed-math helpers ----------------
__device__ __forceinline__ ull ffma2(ull a, ull b, ull c){
    ull d;
    asm("fma.rn.f32x2 %0, %1, %2, %3;" : "=l"(d) : "l"(a), "l"(b), "l"(c));
    return d;
}
__device__ __forceinline__ ull pack2(float lo, float hi){
    ull d;
    asm("mov.b64 %0, {%1, %2};" : "=l"(d) : "f"(lo), "f"(hi));
    return d;
}
__device__ __forceinline__ void unpack2(ull v, float& lo, float& hi){
    asm("mov.b64 {%0, %1}, %2;" : "=f"(lo), "=f"(hi) : "l"(v));
}

// ---------------- scratch ----------------
__device__ float g_WT [7*65536];            // transposed weights [w][kk][d]
__device__ float g_q1 [BB*HH*SS*DKK];
__device__ float g_q1T[BB*HH*DKK*SS];
__device__ float g_v1 [BB*HH*SS*DKK];
__device__ float g_att1[BB*SS*DD];
__device__ float g_p  [BB*SS*DD];
__device__ float g_k4 [BB*HH*SS*DKK];
__device__ float g_k4T[BB*HH*DKK*SS];
__device__ float g_v4 [BB*HH*SS*DKK];
__device__ float g_qh [NKK*DD];
__device__ float g_r4 [BB*NKK*HH*SS];
__device__ float g_P4 [BB*NKK*HH*SS];
__device__ float g_out4[BB*NKK*SS*DD];

// ---------------- helpers ----------------
__device__ __forceinline__ float warpMax(float v){
#pragma unroll
    for (int o = 16; o; o >>= 1) v = fmaxf(v, __shfl_xor_sync(0xffffffffu, v, o));
    return v;
}
__device__ __forceinline__ float warpSum(float v){
#pragma unroll
    for (int o = 16; o; o >>= 1) v += __shfl_xor_sync(0xffffffffu, v, o);
    return v;
}
__device__ __forceinline__ float halfwarpSum(float v){
#pragma unroll
    for (int o = 8; o; o >>= 1) v += __shfl_xor_sync(0xffffffffu, v, o);
    return v;
}
__device__ float blockMax(float v, float* s8, int tid){
    v = warpMax(v);
    if ((tid & 31) == 0) s8[tid >> 5] = v;
    __syncthreads();
    if (tid == 0){
        float m = s8[0];
#pragma unroll
        for (int w = 1; w < 8; w++) m = fmaxf(m, s8[w]);
        s8[0] = m;
    }
    __syncthreads();
    float r = s8[0];
    __syncthreads();
    return r;
}
__device__ float blockSum(float v, float* s8, int tid){
    v = warpSum(v);
    if ((tid & 31) == 0) s8[tid >> 5] = v;
    __syncthreads();
    if (tid == 0){
        float m = 0.f;
#pragma unroll
        for (int w = 0; w < 8; w++) m += s8[w];
        s8[0] = m;
    }
    __syncthreads();
    float r = s8[0];
    __syncthreads();
    return r;
}
// inclusive scan of 512 floats in smem, 256 threads (thread t owns 2t,2t+1)
__device__ void blockScan512(float* sdata, float* swarp, int tid){
    float a0 = sdata[2*tid], a1 = sdata[2*tid+1];
    float ts = a0 + a1;
    float v = ts;
#pragma unroll
    for (int o = 1; o < 32; o <<= 1){
        float n = __shfl_up_sync(0xffffffffu, v, o);
        if ((tid & 31) >= o) v += n;
    }
    if ((tid & 31) == 31) swarp[tid >> 5] = v;
    __syncthreads();
    if (tid < 8){
        float w = swarp[tid];
#pragma unroll
        for (int o = 1; o < 8; o <<= 1){
            float n = __shfl_up_sync(0xffu, w, o);
            if (tid >= o) w += n;
        }
        swarp[tid] = w;
    }
    __syncthreads();
    float base = (tid >= 32) ? swarp[(tid >> 5) - 1] : 0.f;
    float excl = base + (v - ts);
    sdata[2*tid]   = excl + a0;
    sdata[2*tid+1] = excl + a0 + a1;
    __syncthreads();
}

// ---------------- weight transpose:  g_WT[w][kk][d] = W[d][kk] ----------------
__global__ void __launch_bounds__(256) transpose_w_kernel(
        const float* Wq1, const float* Wv1, const float* Wo1,
        const float* Wq4, const float* Wk4, const float* Wv4, const float* Wo4){
    int idx = blockIdx.x * 256 + threadIdx.x;   // 7*65536 total
    int w = idx >> 16, e = idx & 65535;
    int d = e >> 8, kk = e & 255;
    const float* src;
    switch (w){
        case 0: src = Wq1; break;  case 1: src = Wv1; break;
        case 2: src = Wo1; break;  case 3: src = Wq4; break;
        case 4: src = Wk4; break;  case 5: src = Wv4; break;
        default: src = Wo4; break;
    }
    g_WT[w*65536 + kk*256 + d] = src[d*256 + kk];
}

// ---------------- proj2: 32x64 tile GEMM, Y = X @ W^T + b, head layout (+T) ----------------
// grid (rows/32, 4). outsel: 0=q1(+T) 1=v1 2=k4(+T) 3=v4. xsel 1 -> X=g_p
__global__ void __launch_bounds__(256) proj2_kernel(
        const float* Xin, const float* bias, int wsel, int outsel, int xsel){
    __shared__ float Xs[32][34];   // [k][row]
    __shared__ float Ws[32][68];   // [k][n]
    int tid = threadIdx.x;
    int row0 = blockIdx.x * 32;
    int n0   = blockIdx.y * 64;
    const float* X = (xsel == 1) ? g_p : Xin;
    const float* W = g_WT + (size_t)wsel*65536;

    int lr = tid >> 3;           // X load row 0..31
    int lk = (tid & 7) * 4;      // X load k (4 consecutive)
    int wk = tid >> 3;           // W load k row 0..31
    int wn = (tid & 7) * 8;      // W load col (8 consecutive)

    int tc = tid & 15, tr = tid >> 4;
    ull acc[2][2] = {{0ull,0ull},{0ull,0ull}};

    for (int kc = 0; kc < 256; kc += 32){
        float4 xv  = *(const float4*)&X[(size_t)(row0 + lr)*256 + kc + lk];
        float4 wv0 = *(const float4*)&W[(size_t)(kc + wk)*256 + n0 + wn];
        float4 wv1 = *(const float4*)&W[(size_t)(kc + wk)*256 + n0 + wn + 4];
        Xs[lk+0][lr] = xv.x; Xs[lk+1][lr] = xv.y;
        Xs[lk+2][lr] = xv.z; Xs[lk+3][lr] = xv.w;
        *(float4*)&Ws[wk][wn]   = wv0;
        *(float4*)&Ws[wk][wn+4] = wv1;
        __syncthreads();
#pragma unroll
        for (int k = 0; k < 32; k++){
            float2 a = *(const float2*)&Xs[k][tr*2];
            float4 b = *(const float4*)&Ws[k][tc*4];
            ull b01 = pack2(b.x, b.y), b23 = pack2(b.z, b.w);
            ull a0 = pack2(a.x, a.x), a1 = pack2(a.y, a.y);
            acc[0][0] = ffma2(a0, b01, acc[0][0]);
            acc[0][1] = ffma2(a0, b23, acc[0][1]);
            acc[1][0] = ffma2(a1, b01, acc[1][0]);
            acc[1][1] = ffma2(a1, b23, acc[1][1]);
        }
        __syncthreads();
    }

    int n = n0 + tc*4;
    float4 bb = *(const float4*)&bias[n];
    int h = n >> 5, dk = n & 31;
    float* Yh; float* YT = nullptr;
    switch (outsel){
        case 0: Yh = g_q1; YT = g_q1T; break;
        case 1: Yh = g_v1; break;
        case 2: Yh = g_k4; YT = g_k4T; break;
        default: Yh = g_v4; break;
    }
#pragma unroll
    for (int q = 0; q < 2; q++){
        int row = row0 + tr*2 + q;
        int bidx = row >> 9, s = row & 511;
        float y0,y1,y2,y3;
        unpack2(acc[q][0], y0, y1);
        unpack2(acc[q][1], y2, y3);
        float4 v = make_float4(y0 + bb.x, y1 + bb.y, y2 + bb.z, y3 + bb.w);
        *(float4*)&Yh[(((size_t)(bidx*HH + h)*SS + s)*DKK + dk)] = v;
        if (YT){
            size_t tb = (size_t)(bidx*HH + h)*DKK;
            YT[(tb + dk + 0)*SS + s] = v.x;
            YT[(tb + dk + 1)*SS + s] = v.y;
            YT[(tb + dk + 2)*SS + s] = v.z;
            YT[(tb + dk + 3)*SS + s] = v.w;
        }
    }
}

// ---------------- epi2<RT>: (RT*16)x256 tile GEMM + residual + LayerNorm ----------------
// mode 0 (RT=2): X=g_att1, resid=q_emb rowwise, dst=g_p.
// mode 1 (RT=4): X=g_out4, resid=know_params[k], dst=z scatter.
template<int RT>
__global__ void __launch_bounds__(256) epi2_kernel(
        const float* resid, const float* lng, const float* lnb,
        int wsel, const float* bias, int mode, float* dst){
    constexpr int ROWS = RT*16;
    constexpr int XP = (RT == 4) ? 68 : 34;
    __shared__ float Xs[32][XP];     // [k][row]
    __shared__ float Ws[32][264];    // [k][n]
    int tid = threadIdx.x;
    int row0 = blockIdx.x * ROWS;
    const float* Xsrc = (mode == 0) ? g_att1 : g_out4;
    const float* W = g_WT + (size_t)wsel*65536;
    int tc = tid & 15, tr = tid >> 4;

    ull acc[RT][4][2];
#pragma unroll
    for (int r = 0; r < RT; r++)
#pragma unroll
        for (int cb = 0; cb < 4; cb++){ acc[r][cb][0] = 0ull; acc[r][cb][1] = 0ull; }

    int wk = tid >> 4;               // W: rows wk, wk+16; 16 cols each
    int wn = (tid & 15) * 16;

    for (int kc = 0; kc < 256; kc += 32){
        // X tile load (transposed into smem)
        float4 x0, x1;
        int xr, xk;
        if (RT == 4){ xr = tid >> 2; xk = (tid & 3) * 8;
            x0 = *(const float4*)&Xsrc[(size_t)(row0 + xr)*256 + kc + xk];
            x1 = *(const float4*)&Xsrc[(size_t)(row0 + xr)*256 + kc + xk + 4];
        } else { xr = tid >> 3; xk = (tid & 7) * 4;
            x0 = *(const float4*)&Xsrc[(size_t)(row0 + xr)*256 + kc + xk];
        }
        float4 w0 = *(const float4*)&W[(size_t)(kc + wk)*256 + wn];
        float4 w1 = *(const float4*)&W[(size_t)(kc + wk)*256 + wn + 4];
        float4 w2 = *(const float4*)&W[(size_t)(kc + wk)*256 + wn + 8];
        float4 w3 = *(const float4*)&W[(size_t)(kc + wk)*256 + wn + 12];
        float4 w4 = *(const float4*)&W[(size_t)(kc + wk + 16)*256 + wn];
        float4 w5 = *(const float4*)&W[(size_t)(kc + wk + 16)*256 + wn + 4];
        float4 w6 = *(const float4*)&W[(size_t)(kc + wk + 16)*256 + wn + 8];
        float4 w7 = *(const float4*)&W[(size_t)(kc + wk + 16)*256 + wn + 12];
        Xs[xk+0][xr] = x0.x; Xs[xk+1][xr] = x0.y; Xs[xk+2][xr] = x0.z; Xs[xk+3][xr] = x0.w;
        if (RT == 4){
            Xs[xk+4][xr] = x1.x; Xs[xk+5][xr] = x1.y; Xs[xk+6][xr] = x1.z; Xs[xk+7][xr] = x1.w;
        }
        *(float4*)&Ws[wk][wn]      = w0;
        *(float4*)&Ws[wk][wn+4]    = w1;
        *(float4*)&Ws[wk][wn+8]    = w2;
        *(float4*)&Ws[wk][wn+12]   = w3;
        *(float4*)&Ws[wk+16][wn]   = w4;
        *(float4*)&Ws[wk+16][wn+4] = w5;
        *(float4*)&Ws[wk+16][wn+8] = w6;
        *(float4*)&Ws[wk+16][wn+12]= w7;
        __syncthreads();
#pragma unroll
        for (int k = 0; k < 32; k++){
            float a[RT];
            if (RT == 4){
                float4 av = *(const float4*)&Xs[k][tr*4];
                a[0]=av.x; a[1]=av.y; a[2]=av.z; a[3]=av.w;
            } else {
                float2 av = *(const float2*)&Xs[k][tr*2];
                a[0]=av.x; a[1]=av.y;
            }
            ull aa[RT];
#pragma unroll
            for (int r = 0; r < RT; r++) aa[r] = pack2(a[r], a[r]);
#pragma unroll
            for (int cb = 0; cb < 4; cb++){
                float4 b = *(const float4*)&Ws[k][cb*64 + tc*4];
                ull b01 = pack2(b.x, b.y), b23 = pack2(b.z, b.w);
#pragma unroll
                for (int r = 0; r < RT; r++){
                    acc[r][cb][0] = ffma2(aa[r], b01, acc[r][cb][0]);
                    acc[r][cb][1] = ffma2(aa[r], b23, acc[r][cb][1]);
                }
            }
        }
        __syncthreads();
    }

    // ---- epilogue: bias + residual + LayerNorm + store ----
    int nb = tc*4;
    float4 bb[4], lg[4], lb[4];
#pragma unroll
    for (int cb = 0; cb < 4; cb++){
        bb[cb] = *(const float4*)&bias[cb*64 + nb];
        lg[cb] = *(const float4*)&lng [cb*64 + nb];
        lb[cb] = *(const float4*)&lnb [cb*64 + nb];
    }
#pragma unroll
    for (int q = 0; q < RT; q++){
        int row = row0 + tr*RT + q;
        float y[16];
#pragma unroll
        for (int cb = 0; cb < 4; cb++){
            float4 rv;
            if (mode == 0) rv = *(const float4*)&resid[(size_t)row*256 + cb*64 + nb];
            else { int kk = (row >> 9) & 15;
                   rv = *(const float4*)&resid[(size_t)kk*256 + cb*64 + nb]; }
            float a0,a1,a2,a3;
            unpack2(acc[q][cb][0], a0, a1);
            unpack2(acc[q][cb][1], a2, a3);
            y[cb*4+0] = a0 + bb[cb].x + rv.x;
            y[cb*4+1] = a1 + bb[cb].y + rv.y;
            y[cb*4+2] = a2 + bb[cb].z + rv.z;
            y[cb*4+3] = a3 + bb[cb].w + rv.w;
        }
        float s = 0.f;
#pragma unroll
        for (int e = 0; e < 16; e++) s += y[e];
        s = halfwarpSum(s);
        float mean = s * (1.f/256.f);
        float vs = 0.f;
#pragma unroll
        for (int e = 0; e < 16; e++){ float t = y[e] - mean; vs += t*t; }
        vs = halfwarpSum(vs);
        float inv = rsqrtf(vs*(1.f/256.f) + 1e-5f);
        size_t base;
        float* out;
        if (mode == 0){ base = (size_t)row*256; out = g_p; }
        else {
            int b = row >> 13, kk = (row >> 9) & 15, s2 = row & 511;
            base = ((size_t)(b*512 + s2)*16 + kk)*256; out = dst;
        }
#pragma unroll
        for (int cb = 0; cb < 4; cb++){
            float4 o;
            o.x = (y[cb*4+0]-mean)*inv*lg[cb].x + lb[cb].x;
            o.y = (y[cb*4+1]-mean)*inv*lg[cb].y + lb[cb].y;
            o.z = (y[cb*4+2]-mean)*inv*lg[cb].z + lb[cb].z;
            o.w = (y[cb*4+3]-mean)*inv*lg[cb].w + lb[cb].w;
            *(float4*)&out[base + cb*64 + nb] = o;
        }
    }
}

// ---------------- knowledge-query projection: 16 blocks ----------------
__global__ void __launch_bounds__(256) knowproj2_kernel(const float* kp, const float* bq){
    __shared__ float kr[256];
    int k = blockIdx.x, tid = threadIdx.x;
    kr[tid] = kp[k*256 + tid];
    __syncthreads();
    const float* W = g_WT + 3*65536;
    float acc = bq[tid];
#pragma unroll 8
    for (int kk = 0; kk < 256; kk++)
        acc += kr[kk] * W[kk*256 + tid];
    g_qh[k*256 + tid] = acc;
}

// ---------------- block-4 score rows + exp prefix sums ----------------
__global__ void __launch_bounds__(256) r4pre_kernel(){
    int idx = blockIdx.x;                 // (b*16+k)*8+h
    int h = idx & 7, bk = idx >> 3, b = bk >> 4, k = bk & 15;
    int tid = threadIdx.x;
    __shared__ float qv[DKK];
    __shared__ float sbuf[512];
    __shared__ float sred[8];
    if (tid < DKK) qv[tid] = g_qh[k*DD + h*DKK + tid];
    __syncthreads();
    const float* kT = g_k4T + (size_t)(b*HH + h)*DKK*SS;
    int j0 = tid, j1 = tid + 256;
    float r0 = 0.f, r1 = 0.f;
#pragma unroll
    for (int d = 0; d < DKK; d++){
        float q = qv[d];
        r0 += q*kT[d*SS + j0];
        r1 += q*kT[d*SS + j1];
    }
    const float sc = 0.17677669529663687f;  // 1/sqrt(32)
    r0 *= sc; r1 *= sc;
    size_t rb = (size_t)idx*SS;
    g_r4[rb + j0] = r0; g_r4[rb + j1] = r1;
    float M = blockMax(fmaxf(r0, r1), sred, tid);
    sbuf[j0] = expf(r0 - M); sbuf[j1] = expf(r1 - M);
    __syncthreads();
    blockScan512(sbuf, sred, tid);
    g_P4[rb + j0] = sbuf[j0]; g_P4[rb + j1] = sbuf[j1];
}

// ---------------- block-1 attention row kernel (unchanged) ----------------
__global__ void __launch_bounds__(256) attn1_kernel(const float* gam, float* qsc){
    int i = blockIdx.x, h = blockIdx.y, b = blockIdx.z;
    int tid = threadIdx.x;
    __shared__ float qv[DKK];
    __shared__ float sbuf[512];
    __shared__ float sred[8];
    __shared__ float pvred[8*32];
    int bh = b*HH + h;
    if (tid < DKK) qv[tid] = g_q1[((size_t)bh*SS + i)*DKK + tid];
    __syncthreads();
    const float* kT = g_q1T + (size_t)bh*DKK*SS;   // kq_same
    int j0 = tid, j1 = tid + 256;
    bool v0 = (j0 <= i), v1b = (j1 <= i);
    float r0 = 0.f, r1 = 0.f;
    if (v0){
#pragma unroll
        for (int d = 0; d < DKK; d++) r0 += qv[d]*kT[d*SS + j0];
    }
    if (v1b){
#pragma unroll
        for (int d = 0; d < DKK; d++) r1 += qv[d]*kT[d*SS + j1];
    }
    const float sc = 0.17677669529663687f;
    r0 *= sc; r1 *= sc;
    float m1 = blockMax(fmaxf(v0 ? r0 : -FLT_MAX, v1b ? r1 : -FLT_MAX), sred, tid);
    float e0 = v0  ? expf(r0 - m1) : 0.f;
    float e1 = v1b ? expf(r1 - m1) : 0.f;
    sbuf[j0] = e0; sbuf[j1] = e1;
    __syncthreads();
    blockScan512(sbuf, sred, tid);            // inclusive prefix of exp
    float Z = sbuf[i], invZ = 1.f / Z;
    float PE0 = sbuf[j0], PE1 = sbuf[j1];
    float g = fabsf(gam[h]);
    float s20 = -FLT_MAX, s21 = -FLT_MAX;
    if (v0){
        float tail = fmaxf((Z - PE0)*invZ, 0.f);
        float u = tail * (float)(i - j0);
        float eff = fminf(fmaxf(expf(-g*sqrtf(fmaxf(u, 0.f))), 1e-5f), 1e5f);
        s20 = r0*eff;
    }
    if (v1b){
        float tail = fmaxf((Z - PE1)*invZ, 0.f);
        float u = tail * (float)(i - j1);
        float eff = fminf(fmaxf(expf(-g*sqrtf(fmaxf(u, 0.f))), 1e-5f), 1e5f);
        s21 = r1*eff;
    }
    float m2 = blockMax(fmaxf(s20, s21), sred, tid);
    float f0 = v0  ? expf(s20 - m2) : 0.f;
    float f1 = v1b ? expf(s21 - m2) : 0.f;
    float Z2 = blockSum(f0 + f1, sred, tid);
    float invZ2 = 1.f / Z2;
    float p0 = f0*invZ2, p1 = f1*invZ2;
    size_t qrow = ((size_t)bh*SS + i)*SS;
    qsc[qrow + j0] = p0;
    qsc[qrow + j1] = p1;
    sbuf[j0] = p0; sbuf[j1] = p1;
    __syncthreads();
    int d = tid & 31, grp = tid >> 5;
    const float* vrow = g_v1 + (size_t)bh*SS*DKK;
    float acc = 0.f;
    for (int j = grp; j <= i; j += 8) acc += sbuf[j]*vrow[j*DKK + d];
    pvred[grp*32 + d] = acc;
    __syncthreads();
    if (tid < 32){
        float a = 0.f;
#pragma unroll
        for (int g2 = 0; g2 < 8; g2++) a += pvred[g2*32 + tid];
        g_att1[((size_t)b*SS + i)*DD + h*DKK + tid] = a;
    }
}

// ---------------- block-4 attention: tiled flash-style kernel (unchanged) ----------------
__global__ void __launch_bounds__(256) attn4_kernel(const float* gam, float* ksc){
    int tile = blockIdx.x;
    int k    = blockIdx.y;
    int bh   = blockIdx.z;          // b*8+h
    int b = bh >> 3, h = bh & 7;
    int tid = threadIdx.x;
    int lane = tid & 31, w = tid >> 5;
    int i0 = tile * TI;
    int Jlim = i0 + TI;

    __shared__ float r_s[SS];
    __shared__ float P_s[SS];
    __shared__ float p_s[64][130];
    __shared__ float m2_s[TI], sc_s[TI], is_s[TI];

    size_t rb = ((size_t)((b*NKK + k)*HH + h)) * SS;
    for (int j = tid; j < SS; j += 256){
        r_s[j] = g_r4[rb + j];
        P_s[j] = g_P4[rb + j];
    }
    __syncthreads();

    float g = fabsf(gam[h]);

    for (int m = 0; m < TI/8; m++){
        int ii = w + 8*m;
        int i  = i0 + ii;
        float invS1 = (i > 0) ? 1.f / P_s[i-1] : 0.f;
        float s2v[16];
        float mx = -FLT_MAX;
#pragma unroll
        for (int c = 0; c < 16; c++){
            s2v[c] = -FLT_MAX;
            if (c*32 < i){
                int j = lane + 32*c;
                if (j < i){
                    float r = r_s[j];
                    float tail = fmaxf(1.f - P_s[j]*invS1, 0.f);
                    float u = tail * (float)(i - j);
                    float eff = fminf(fmaxf(__expf(-g*sqrtf(u)), 1e-5f), 1e5f);
                    float s2 = r*eff;
                    s2v[c] = s2;
                    mx = fmaxf(mx, s2);
                }
            }
        }
        float m2 = warpMax(mx);
        float Zp = 0.f;
#pragma unroll
        for (int c = 0; c < 16; c++)
            if (c*32 < i) Zp += __expf(s2v[c] - m2);
        float Z = warpSum(Zp);
        if (lane == 0){
            m2_s[ii] = m2;
            sc_s[ii] = (Z > 0.f) ? fminf(Z, 5.f)/Z : 0.f;
            is_s[ii] = invS1;
        }
    }
    __syncthreads();

    size_t kbase0 = (((size_t)(b*HH + h)*SS + i0)*NKK + k)*SS;

    if (Jlim < SS){
        for (int m = 0; m < TI/8; m++){
            int ii = w + 8*m;
            float4* dst = (float4*)(ksc + kbase0 + (size_t)ii*(NKK*SS));
            for (int j4 = (Jlim >> 2) + lane; j4 < (SS >> 2); j4 += 32)
                dst[j4] = make_float4(0.f, 0.f, 0.f, 0.f);
        }
    }

    int d0  = (tid & 7) * 4;
    int ii0 = (tid >> 3) * 4;
    ull acc2[2][4];
#pragma unroll
    for (int q = 0; q < 2; q++)
#pragma unroll
        for (int dc = 0; dc < 4; dc++) acc2[q][dc] = 0ull;
    const float* vbase = g_v4 + (size_t)bh*SS*DKK;
    int ilimT = i0 + ii0 + 4;

    for (int jc = 0; jc < Jlim; jc += 64){
        for (int m = 0; m < TI/8; m++){
            int ii = w + 8*m;
            int i  = i0 + ii;
            float m2 = m2_s[ii], sc = sc_s[ii], invS1 = is_s[ii];
            float* krow = ksc + kbase0 + (size_t)ii*(NKK*SS);
#pragma unroll
            for (int q = 0; q < 2; q++){
                int j = jc + lane + 32*q;
                float p = 0.f;
                if (j < i){
                    float r = r_s[j];
                    float tail = fmaxf(1.f - P_s[j]*invS1, 0.f);
                    float u = tail * (float)(i - j);
                    float eff = fminf(fmaxf(__expf(-g*sqrtf(u)), 1e-5f), 1e5f);
                    p = __expf(r*eff - m2) * sc;
                }
                p_s[j - jc][ii] = p;
                krow[j] = p;
            }
        }
        __syncthreads();
        if (jc < ilimT){
#pragma unroll 2
            for (int jj = 0; jj < 64; jj++){
                float4 v = *(const float4*)(vbase + (size_t)(jc + jj)*DKK + d0);
                ull vx = pack2(v.x, v.x), vy = pack2(v.y, v.y);
                ull vz = pack2(v.z, v.z), vw = pack2(v.w, v.w);
#pragma unroll
                for (int q = 0; q < 2; q++){
                    ull pp = *(const ull*)&p_s[jj][ii0 + 2*q];
                    acc2[q][0] = ffma2(pp, vx, acc2[q][0]);
                    acc2[q][1] = ffma2(pp, vy, acc2[q][1]);
                    acc2[q][2] = ffma2(pp, vz, acc2[q][2]);
                    acc2[q][3] = ffma2(pp, vw, acc2[q][3]);
                }
            }
        }
        __syncthreads();
    }

    float va[4][4];
#pragma unroll
    for (int q = 0; q < 2; q++)
#pragma unroll
        for (int dc = 0; dc < 4; dc++)
            unpack2(acc2[q][dc], va[2*q][dc], va[2*q+1][dc]);
    float* obase = g_out4 + ((size_t)(b*NKK + k)*SS)*DD + h*DKK;
#pragma unroll
    for (int r = 0; r < 4; r++){
        *(float4*)(obase + (size_t)(i0 + ii0 + r)*DD + d0) =
            make_float4(va[r][0], va[r][1], va[r][2], va[r][3]);
    }
}

// ---------------- launch ----------------
extern "C" void kernel_launch(void* const* d_in, const int* in_sizes, int n_in,
                              void* d_out, int out_size){
    (void)in_sizes; (void)n_in; (void)out_size;
    const float* q_emb = (const float*)d_in[0];
    const float* s_emb = (const float*)d_in[1];
    const float* Wq1 = (const float*)d_in[5];
    const float* bq1 = (const float*)d_in[6];
    const float* Wv1 = (const float*)d_in[7];
    const float* bv1 = (const float*)d_in[8];
    const float* Wo1 = (const float*)d_in[9];
    const float* bo1 = (const float*)d_in[10];
    const float* gam1= (const float*)d_in[11];
    const float* ln1g= (const float*)d_in[12];
    const float* ln1b= (const float*)d_in[13];
    const float* Wq4 = (const float*)d_in[14];
    const float* bq4 = (const float*)d_in[15];
    const float* Wk4 = (const float*)d_in[16];
    const float* bk4 = (const float*)d_in[17];
    const float* Wv4 = (const float*)d_in[18];
    const float* bv4 = (const float*)d_in[19];
    const float* Wo4 = (const float*)d_in[20];
    const float* bo4 = (const float*)d_in[21];
    const float* gam4= (const float*)d_in[22];
    const float* ln4g= (const float*)d_in[23];
    const float* ln4b= (const float*)d_in[24];
    const float* knowp=(const float*)d_in[25];

    float* out  = (float*)d_out;
    float* z_out = out;                       // [B,S,NK*D]
    float* q_out = out + Z_ELEMS;             // [B,H,S,S]
    float* k_out = out + Z_ELEMS + Q_ELEMS;   // [B,H,S,NK,S]

    transpose_w_kernel<<<1792, 256>>>(Wq1, Wv1, Wo1, Wq4, Wk4, Wv4, Wo4);
    // block-4-independent precompute first (keeps deps simple)
    proj2_kernel<<<dim3(32,4), 256>>>(q_emb, bk4, 4, 2, 0);   // k4 (+T)
    knowproj2_kernel<<<16, 256>>>(knowp, bq4);
    r4pre_kernel<<<256, 256>>>();
    // block 1
    proj2_kernel<<<dim3(32,4), 256>>>(q_emb, bq1, 0, 0, 0);   // q1 (+T); k1 == q1
    proj2_kernel<<<dim3(32,4), 256>>>(s_emb, bv1, 1, 1, 0);   // v1
    attn1_kernel<<<dim3(SS, HH, BB), 256>>>(gam1, q_out);
    epi2_kernel<2><<<32, 256>>>(q_emb, ln1g, ln1b, 2, bo1, 0, nullptr);   // -> g_p
    // block 4
    proj2_kernel<<<dim3(32,4), 256>>>(nullptr, bv4, 5, 3, 1); // v4 from g_p
    attn4_kernel<<<dim3(4, NKK, BB*HH), 256>>>(gam4, k_out);
    epi2_kernel<4><<<256, 256>>>(knowp, ln4g, ln4b, 6, bo4, 1, z_out);    // -> z
}

// round 5
// speedup vs baseline: 1.9534x; 1.1111x over previous
#include <cuda_runtime.h>
#include <math.h>
#include <float.h>

#define BB  2
#define SS  512
#define DD  256
#define HH  8
#define DKK 32
#define NKK 16
#define TI  128

#define Z_ELEMS (BB*SS*NKK*DD)   // 4194304
#define Q_ELEMS (BB*HH*SS*SS)    // 4194304

typedef unsigned long long ull;

// ---------------- f32x2 packed-math helpers ----------------
__device__ __forceinline__ ull ffma2(ull a, ull b, ull c){
    ull d;
    asm("fma.rn.f32x2 %0, %1, %2, %3;" : "=l"(d) : "l"(a), "l"(b), "l"(c));
    return d;
}
__device__ __forceinline__ ull pack2(float lo, float hi){
    ull d;
    asm("mov.b64 %0, {%1, %2};" : "=l"(d) : "f"(lo), "f"(hi));
    return d;
}
__device__ __forceinline__ void unpack2(ull v, float& lo, float& hi){
    asm("mov.b64 {%0, %1}, %2;" : "=f"(lo), "=f"(hi) : "l"(v));
}
__device__ __forceinline__ float fsqrt_fast(float x){
    float y;
    asm("sqrt.approx.f32 %0, %1;" : "=f"(y) : "f"(x));
    return y;
}

// ---------------- scratch ----------------
__device__ float g_WT [7*65536];            // transposed weights [w][kk][d]
__device__ float g_q1 [BB*HH*SS*DKK];
__device__ float g_q1T[BB*HH*DKK*SS];
__device__ float g_v1 [BB*HH*SS*DKK];
__device__ float g_att1[BB*SS*DD];
__device__ float g_p  [BB*SS*DD];
__device__ float g_k4 [BB*HH*SS*DKK];
__device__ float g_k4T[BB*HH*DKK*SS];
__device__ float g_v4 [BB*HH*SS*DKK];
__device__ float g_qh [NKK*DD];
__device__ float g_r4 [BB*NKK*HH*SS];
__device__ float g_P4 [BB*NKK*HH*SS];
__device__ float g_out4[BB*NKK*SS*DD];

// ---------------- helpers ----------------
__device__ __forceinline__ float warpMax(float v){
#pragma unroll
    for (int o = 16; o; o >>= 1) v = fmaxf(v, __shfl_xor_sync(0xffffffffu, v, o));
    return v;
}
__device__ __forceinline__ float warpSum(float v){
#pragma unroll
    for (int o = 16; o; o >>= 1) v += __shfl_xor_sync(0xffffffffu, v, o);
    return v;
}
__device__ __forceinline__ float halfwarpSum(float v){
#pragma unroll
    for (int o = 8; o; o >>= 1) v += __shfl_xor_sync(0xffffffffu, v, o);
    return v;
}
__device__ float blockSum(float v, float* s8, int tid){
    v = warpSum(v);
    if ((tid & 31) == 0) s8[tid >> 5] = v;
    __syncthreads();
    if (tid == 0){
        float m = 0.f;
#pragma unroll
        for (int w = 0; w < 8; w++) m += s8[w];
        s8[0] = m;
    }
    __syncthreads();
    float r = s8[0];
    __syncthreads();
    return r;
}
// inclusive scan of 512 floats in smem, 256 threads (thread t owns 2t,2t+1)
__device__ void blockScan512(float* sdata, float* swarp, int tid){
    float a0 = sdata[2*tid], a1 = sdata[2*tid+1];
    float ts = a0 + a1;
    float v = ts;
#pragma unroll
    for (int o = 1; o < 32; o <<= 1){
        float n = __shfl_up_sync(0xffffffffu, v, o);
        if ((tid & 31) >= o) v += n;
    }
    if ((tid & 31) == 31) swarp[tid >> 5] = v;
    __syncthreads();
    if (tid < 8){
        float w = swarp[tid];
#pragma unroll
        for (int o = 1; o < 8; o <<= 1){
            float n = __shfl_up_sync(0xffu, w, o);
            if (tid >= o) w += n;
        }
        swarp[tid] = w;
    }
    __syncthreads();
    float base = (tid >= 32) ? swarp[(tid >> 5) - 1] : 0.f;
    float excl = base + (v - ts);
    sdata[2*tid]   = excl + a0;
    sdata[2*tid+1] = excl + a0 + a1;
    __syncthreads();
}

// ---------------- weight transpose:  g_WT[w][kk][d] = W[d][kk] ----------------
__global__ void __launch_bounds__(256) transpose_w_kernel(
        const float* Wq1, const float* Wv1, const float* Wo1,
        const float* Wq4, const float* Wk4, const float* Wv4, const float* Wo4){
    int idx = blockIdx.x * 256 + threadIdx.x;   // 7*65536 total
    int w = idx >> 16, e = idx & 65535;
    int d = e >> 8, kk = e & 255;
    const float* src;
    switch (w){
        case 0: src = Wq1; break;  case 1: src = Wv1; break;
        case 2: src = Wo1; break;  case 3: src = Wq4; break;
        case 4: src = Wk4; break;  case 5: src = Wv4; break;
        default: src = Wo4; break;
    }
    g_WT[w*65536 + kk*256 + d] = src[d*256 + kk];
}

// ---------------- proj2: 32x64 tile GEMM, Y = X @ W^T + b, head layout (+T) ----------------
__global__ void __launch_bounds__(256) proj2_kernel(
        const float* Xin, const float* bias, int wsel, int outsel, int xsel){
    __shared__ float Xs[32][34];   // [k][row]
    __shared__ float Ws[32][68];   // [k][n]
    int tid = threadIdx.x;
    int row0 = blockIdx.x * 32;
    int n0   = blockIdx.y * 64;
    const float* X = (xsel == 1) ? g_p : Xin;
    const float* W = g_WT + (size_t)wsel*65536;

    int lr = tid >> 3;
    int lk = (tid & 7) * 4;
    int wk = tid >> 3;
    int wn = (tid & 7) * 8;

    int tc = tid & 15, tr = tid >> 4;
    ull acc[2][2] = {{0ull,0ull},{0ull,0ull}};

    for (int kc = 0; kc < 256; kc += 32){
        float4 xv  = *(const float4*)&X[(size_t)(row0 + lr)*256 + kc + lk];
        float4 wv0 = *(const float4*)&W[(size_t)(kc + wk)*256 + n0 + wn];
        float4 wv1 = *(const float4*)&W[(size_t)(kc + wk)*256 + n0 + wn + 4];
        Xs[lk+0][lr] = xv.x; Xs[lk+1][lr] = xv.y;
        Xs[lk+2][lr] = xv.z; Xs[lk+3][lr] = xv.w;
        *(float4*)&Ws[wk][wn]   = wv0;
        *(float4*)&Ws[wk][wn+4] = wv1;
        __syncthreads();
#pragma unroll
        for (int k = 0; k < 32; k++){
            float2 a = *(const float2*)&Xs[k][tr*2];
            float4 b = *(const float4*)&Ws[k][tc*4];
            ull b01 = pack2(b.x, b.y), b23 = pack2(b.z, b.w);
            ull a0 = pack2(a.x, a.x), a1 = pack2(a.y, a.y);
            acc[0][0] = ffma2(a0, b01, acc[0][0]);
            acc[0][1] = ffma2(a0, b23, acc[0][1]);
            acc[1][0] = ffma2(a1, b01, acc[1][0]);
            acc[1][1] = ffma2(a1, b23, acc[1][1]);
        }
        __syncthreads();
    }

    int n = n0 + tc*4;
    float4 bb = *(const float4*)&bias[n];
    int h = n >> 5, dk = n & 31;
    float* Yh; float* YT = nullptr;
    switch (outsel){
        case 0: Yh = g_q1; YT = g_q1T; break;
        case 1: Yh = g_v1; break;
        case 2: Yh = g_k4; YT = g_k4T; break;
        default: Yh = g_v4; break;
    }
#pragma unroll
    for (int q = 0; q < 2; q++){
        int row = row0 + tr*2 + q;
        int bidx = row >> 9, s = row & 511;
        float y0,y1,y2,y3;
        unpack2(acc[q][0], y0, y1);
        unpack2(acc[q][1], y2, y3);
        float4 v = make_float4(y0 + bb.x, y1 + bb.y, y2 + bb.z, y3 + bb.w);
        *(float4*)&Yh[(((size_t)(bidx*HH + h)*SS + s)*DKK + dk)] = v;
        if (YT){
            size_t tb = (size_t)(bidx*HH + h)*DKK;
            YT[(tb + dk + 0)*SS + s] = v.x;
            YT[(tb + dk + 1)*SS + s] = v.y;
            YT[(tb + dk + 2)*SS + s] = v.z;
            YT[(tb + dk + 3)*SS + s] = v.w;
        }
    }
}

// ---------------- epi2<RT>: (RT*16)x256 tile GEMM + residual + LayerNorm ----------------
template<int RT>
__global__ void __launch_bounds__(256) epi2_kernel(
        const float* resid, const float* lng, const float* lnb,
        int wsel, const float* bias, int mode, float* dst){
    constexpr int ROWS = RT*16;
    constexpr int XP = (RT == 4) ? 68 : 34;
    __shared__ float Xs[32][XP];
    __shared__ float Ws[32][264];
    int tid = threadIdx.x;
    int row0 = blockIdx.x * ROWS;
    const float* Xsrc = (mode == 0) ? g_att1 : g_out4;
    const float* W = g_WT + (size_t)wsel*65536;
    int tc = tid & 15, tr = tid >> 4;

    ull acc[RT][4][2];
#pragma unroll
    for (int r = 0; r < RT; r++)
#pragma unroll
        for (int cb = 0; cb < 4; cb++){ acc[r][cb][0] = 0ull; acc[r][cb][1] = 0ull; }

    int wk = tid >> 4;
    int wn = (tid & 15) * 16;

    for (int kc = 0; kc < 256; kc += 32){
        float4 x0, x1;
        int xr, xk;
        if (RT == 4){ xr = tid >> 2; xk = (tid & 3) * 8;
            x0 = *(const float4*)&Xsrc[(size_t)(row0 + xr)*256 + kc + xk];
            x1 = *(const float4*)&Xsrc[(size_t)(row0 + xr)*256 + kc + xk + 4];
        } else { xr = tid >> 3; xk = (tid & 7) * 4;
            x0 = *(const float4*)&Xsrc[(size_t)(row0 + xr)*256 + kc + xk];
        }
        float4 w0 = *(const float4*)&W[(size_t)(kc + wk)*256 + wn];
        float4 w1 = *(const float4*)&W[(size_t)(kc + wk)*256 + wn + 4];
        float4 w2 = *(const float4*)&W[(size_t)(kc + wk)*256 + wn + 8];
        float4 w3 = *(const float4*)&W[(size_t)(kc + wk)*256 + wn + 12];
        float4 w4 = *(const float4*)&W[(size_t)(kc + wk + 16)*256 + wn];
        float4 w5 = *(const float4*)&W[(size_t)(kc + wk + 16)*256 + wn + 4];
        float4 w6 = *(const float4*)&W[(size_t)(kc + wk + 16)*256 + wn + 8];
        float4 w7 = *(const float4*)&W[(size_t)(kc + wk + 16)*256 + wn + 12];
        Xs[xk+0][xr] = x0.x; Xs[xk+1][xr] = x0.y; Xs[xk+2][xr] = x0.z; Xs[xk+3][xr] = x0.w;
        if (RT == 4){
            Xs[xk+4][xr] = x1.x; Xs[xk+5][xr] = x1.y; Xs[xk+6][xr] = x1.z; Xs[xk+7][xr] = x1.w;
        }
        *(float4*)&Ws[wk][wn]      = w0;
        *(float4*)&Ws[wk][wn+4]    = w1;
        *(float4*)&Ws[wk][wn+8]    = w2;
        *(float4*)&Ws[wk][wn+12]   = w3;
        *(float4*)&Ws[wk+16][wn]   = w4;
        *(float4*)&Ws[wk+16][wn+4] = w5;
        *(float4*)&Ws[wk+16][wn+8] = w6;
        *(float4*)&Ws[wk+16][wn+12]= w7;
        __syncthreads();
#pragma unroll
        for (int k = 0; k < 32; k++){
            float a[RT];
            if (RT == 4){
                float4 av = *(const float4*)&Xs[k][tr*4];
                a[0]=av.x; a[1]=av.y; a[2]=av.z; a[3]=av.w;
            } else {
                float2 av = *(const float2*)&Xs[k][tr*2];
                a[0]=av.x; a[1]=av.y;
            }
            ull aa[RT];
#pragma unroll
            for (int r = 0; r < RT; r++) aa[r] = pack2(a[r], a[r]);
#pragma unroll
            for (int cb = 0; cb < 4; cb++){
                float4 b = *(const float4*)&Ws[k][cb*64 + tc*4];
                ull b01 = pack2(b.x, b.y), b23 = pack2(b.z, b.w);
#pragma unroll
                for (int r = 0; r < RT; r++){
                    acc[r][cb][0] = ffma2(aa[r], b01, acc[r][cb][0]);
                    acc[r][cb][1] = ffma2(aa[r], b23, acc[r][cb][1]);
                }
            }
        }
        __syncthreads();
    }

    int nb = tc*4;
    float4 bb[4], lg[4], lb[4];
#pragma unroll
    for (int cb = 0; cb < 4; cb++){
        bb[cb] = *(const float4*)&bias[cb*64 + nb];
        lg[cb] = *(const float4*)&lng [cb*64 + nb];
        lb[cb] = *(const float4*)&lnb [cb*64 + nb];
    }
#pragma unroll
    for (int q = 0; q < RT; q++){
        int row = row0 + tr*RT + q;
        float y[16];
#pragma unroll
        for (int cb = 0; cb < 4; cb++){
            float4 rv;
            if (mode == 0) rv = *(const float4*)&resid[(size_t)row*256 + cb*64 + nb];
            else { int kk = (row >> 9) & 15;
                   rv = *(const float4*)&resid[(size_t)kk*256 + cb*64 + nb]; }
            float a0,a1,a2,a3;
            unpack2(acc[q][cb][0], a0, a1);
            unpack2(acc[q][cb][1], a2, a3);
            y[cb*4+0] = a0 + bb[cb].x + rv.x;
            y[cb*4+1] = a1 + bb[cb].y + rv.y;
            y[cb*4+2] = a2 + bb[cb].z + rv.z;
            y[cb*4+3] = a3 + bb[cb].w + rv.w;
        }
        float s = 0.f;
#pragma unroll
        for (int e = 0; e < 16; e++) s += y[e];
        s = halfwarpSum(s);
        float mean = s * (1.f/256.f);
        float vs = 0.f;
#pragma unroll
        for (int e = 0; e < 16; e++){ float t = y[e] - mean; vs += t*t; }
        vs = halfwarpSum(vs);
        float inv = rsqrtf(vs*(1.f/256.f) + 1e-5f);
        size_t base;
        float* out;
        if (mode == 0){ base = (size_t)row*256; out = g_p; }
        else {
            int b = row >> 13, kk = (row >> 9) & 15, s2 = row & 511;
            base = ((size_t)(b*512 + s2)*16 + kk)*256; out = dst;
        }
#pragma unroll
        for (int cb = 0; cb < 4; cb++){
            float4 o;
            o.x = (y[cb*4+0]-mean)*inv*lg[cb].x + lb[cb].x;
            o.y = (y[cb*4+1]-mean)*inv*lg[cb].y + lb[cb].y;
            o.z = (y[cb*4+2]-mean)*inv*lg[cb].z + lb[cb].z;
            o.w = (y[cb*4+3]-mean)*inv*lg[cb].w + lb[cb].w;
            *(float4*)&out[base + cb*64 + nb] = o;
        }
    }
}

// ---------------- knowledge-query projection: 16 blocks ----------------
__global__ void __launch_bounds__(256) knowproj2_kernel(const float* kp, const float* bq){
    __shared__ float kr[256];
    int k = blockIdx.x, tid = threadIdx.x;
    kr[tid] = kp[k*256 + tid];
    __syncthreads();
    const float* W = g_WT + 3*65536;
    float acc = bq[tid];
#pragma unroll 8
    for (int kk = 0; kk < 256; kk++)
        acc += kr[kk] * W[kk*256 + tid];
    g_qh[k*256 + tid] = acc;
}

// ---------------- block-4 score rows + exp prefix sums ----------------
__global__ void __launch_bounds__(256) r4pre_kernel(){
    int idx = blockIdx.x;                 // (b*16+k)*8+h
    int h = idx & 7, bk = idx >> 3, b = bk >> 4, k = bk & 15;
    int tid = threadIdx.x;
    __shared__ float qv[DKK];
    __shared__ float sbuf[512];
    __shared__ float sred[8];
    if (tid < DKK) qv[tid] = g_qh[k*DD + h*DKK + tid];
    __syncthreads();
    const float* kT = g_k4T + (size_t)(b*HH + h)*DKK*SS;
    int j0 = tid, j1 = tid + 256;
    float r0 = 0.f, r1 = 0.f;
#pragma unroll
    for (int d = 0; d < DKK; d++){
        float q = qv[d];
        r0 += q*kT[d*SS + j0];
        r1 += q*kT[d*SS + j1];
    }
    const float sc = 0.17677669529663687f;  // 1/sqrt(32)
    r0 *= sc; r1 *= sc;
    size_t rb = (size_t)idx*SS;
    g_r4[rb + j0] = r0; g_r4[rb + j1] = r1;
    // no max subtraction: all downstream uses are scale-invariant ratios
    sbuf[j0] = __expf(r0); sbuf[j1] = __expf(r1);
    __syncthreads();
    blockScan512(sbuf, sred, tid);
    g_P4[rb + j0] = sbuf[j0]; g_P4[rb + j1] = sbuf[j1];
}

// ---------------- block-1 attention row kernel (fast-math, no max-subtract) --------
__global__ void __launch_bounds__(256) attn1_kernel(const float* gam, float* qsc){
    int i = blockIdx.x, h = blockIdx.y, b = blockIdx.z;
    int tid = threadIdx.x;
    __shared__ float qv[DKK];
    __shared__ float sbuf[512];
    __shared__ float sred[8];
    __shared__ float pvred[8*32];
    int bh = b*HH + h;
    if (tid < DKK) qv[tid] = g_q1[((size_t)bh*SS + i)*DKK + tid];
    __syncthreads();
    const float* kT = g_q1T + (size_t)bh*DKK*SS;   // kq_same
    int j0 = tid, j1 = tid + 256;
    bool v0 = (j0 <= i), v1b = (j1 <= i);
    float r0 = 0.f, r1 = 0.f;
    if (v0){
#pragma unroll
        for (int d = 0; d < DKK; d++) r0 += qv[d]*kT[d*SS + j0];
    }
    if (v1b){
#pragma unroll
        for (int d = 0; d < DKK; d++) r1 += qv[d]*kT[d*SS + j1];
    }
    const float sc = 0.17677669529663687f;
    r0 *= sc; r1 *= sc;
    float e0 = v0  ? __expf(r0) : 0.f;
    float e1 = v1b ? __expf(r1) : 0.f;
    sbuf[j0] = e0; sbuf[j1] = e1;
    __syncthreads();
    blockScan512(sbuf, sred, tid);            // inclusive prefix of exp
    float Z = sbuf[i], invZ = 1.f / Z;
    float PE0 = sbuf[j0], PE1 = sbuf[j1];
    float g = fabsf(gam[h]);
    float f0 = 0.f, f1 = 0.f;
    if (v0){
        float tail = fmaxf((Z - PE0)*invZ, 0.f);
        float u = tail * (float)(i - j0);
        float eff = fmaxf(__expf(-g*fsqrt_fast(u)), 1e-5f);
        f0 = __expf(r0*eff);
    }
    if (v1b){
        float tail = fmaxf((Z - PE1)*invZ, 0.f);
        float u = tail * (float)(i - j1);
        float eff = fmaxf(__expf(-g*fsqrt_fast(u)), 1e-5f);
        f1 = __expf(r1*eff);
    }
    float Z2 = blockSum(f0 + f1, sred, tid);
    float invZ2 = 1.f / Z2;
    float p0 = f0*invZ2, p1 = f1*invZ2;
    size_t qrow = ((size_t)bh*SS + i)*SS;
    qsc[qrow + j0] = p0;
    qsc[qrow + j1] = p1;
    sbuf[j0] = p0; sbuf[j1] = p1;
    __syncthreads();
    int d = tid & 31, grp = tid >> 5;
    const float* vrow = g_v1 + (size_t)bh*SS*DKK;
    float acc = 0.f;
    for (int j = grp; j <= i; j += 8) acc += sbuf[j]*vrow[j*DKK + d];
    pvred[grp*32 + d] = acc;
    __syncthreads();
    if (tid < 32){
        float a = 0.f;
#pragma unroll
        for (int g2 = 0; g2 < 8; g2++) a += pvred[g2*32 + tid];
        g_att1[((size_t)b*SS + i)*DD + h*DKK + tid] = a;
    }
}

// ---------------- block-4 attention: tiled flash-style kernel ----------------
__global__ void __launch_bounds__(256) attn4_kernel(const float* gam, float* ksc){
    int tile = blockIdx.x;
    int k    = blockIdx.y;
    int bh   = blockIdx.z;          // b*8+h
    int b = bh >> 3, h = bh & 7;
    int tid = threadIdx.x;
    int lane = tid & 31, w = tid >> 5;
    int i0 = tile * TI;
    int Jlim = i0 + TI;

    __shared__ float r_s[SS];
    __shared__ float P_s[SS];
    __shared__ float p_s[64][130];
    __shared__ float C_s[TI], is_s[TI];

    size_t rb = ((size_t)((b*NKK + k)*HH + h)) * SS;
    for (int j = tid; j < SS; j += 256){
        r_s[j] = g_r4[rb + j];
        P_s[j] = g_P4[rb + j];
    }
    __syncthreads();

    float g = fabsf(gam[h]);

    // ---- stats: warp-per-row, single sweep (no max-subtraction needed before exp) ----
    for (int m = 0; m < TI/8; m++){
        int ii = w + 8*m;
        int i  = i0 + ii;
        float invS1 = (i > 0) ? 1.f / P_s[i-1] : 0.f;
        float mx = -FLT_MAX;
        float Zp = 0.f;
#pragma unroll
        for (int c = 0; c < 16; c++){
            if (c*32 < i){
                int j = lane + 32*c;
                if (j < i){
                    float r = r_s[j];
                    float tail = fmaxf(1.f - P_s[j]*invS1, 0.f);
                    float u = tail * (float)(i - j);
                    float eff = fmaxf(__expf(-g*fsqrt_fast(u)), 1e-5f);
                    float s2 = r*eff;
                    mx = fmaxf(mx, s2);
                    Zp += __expf(s2);
                }
            }
        }
        float m2 = warpMax(mx);
        float Z = warpSum(Zp);
        if (lane == 0){
            // maxout: p = exp(s2)/Z * min(Z/exp(m2), 5)  ->  p = exp(s2) * C
            float C = 0.f;
            if (Z > 0.f) C = fminf(Z * __expf(-m2), 5.f) / Z;
            C_s[ii]  = C;
            is_s[ii] = invS1;
        }
    }
    __syncthreads();

    size_t kbase0 = (((size_t)(b*HH + h)*SS + i0)*NKK + k)*SS;

    if (Jlim < SS){
        for (int m = 0; m < TI/8; m++){
            int ii = w + 8*m;
            float4* dst = (float4*)(ksc + kbase0 + (size_t)ii*(NKK*SS));
            for (int j4 = (Jlim >> 2) + lane; j4 < (SS >> 2); j4 += 32)
                dst[j4] = make_float4(0.f, 0.f, 0.f, 0.f);
        }
    }

    int d0  = (tid & 7) * 4;
    int ii0 = (tid >> 3) * 4;
    ull acc2[2][4];
#pragma unroll
    for (int q = 0; q < 2; q++)
#pragma unroll
        for (int dc = 0; dc < 4; dc++) acc2[q][dc] = 0ull;
    const float* vbase = g_v4 + (size_t)bh*SS*DKK;
    int ilimT = i0 + ii0 + 4;

    for (int jc = 0; jc < Jlim; jc += 64){
        for (int m = 0; m < TI/8; m++){
            int ii = w + 8*m;
            int i  = i0 + ii;
            float C = C_s[ii], invS1 = is_s[ii];
            float* krow = ksc + kbase0 + (size_t)ii*(NKK*SS);
#pragma unroll
            for (int q = 0; q < 2; q++){
                int j = jc + lane + 32*q;
                float p = 0.f;
                if (j < i){
                    float r = r_s[j];
                    float tail = fmaxf(1.f - P_s[j]*invS1, 0.f);
                    float u = tail * (float)(i - j);
                    float eff = fmaxf(__expf(-g*fsqrt_fast(u)), 1e-5f);
                    p = __expf(r*eff) * C;
                }
                p_s[j - jc][ii] = p;
                krow[j] = p;
            }
        }
        __syncthreads();
        if (jc < ilimT){
#pragma unroll 2
            for (int jj = 0; jj < 64; jj++){
                float4 v = *(const float4*)(vbase + (size_t)(jc + jj)*DKK + d0);
                ull vx = pack2(v.x, v.x), vy = pack2(v.y, v.y);
                ull vz = pack2(v.z, v.z), vw = pack2(v.w, v.w);
#pragma unroll
                for (int q = 0; q < 2; q++){
                    ull pp = *(const ull*)&p_s[jj][ii0 + 2*q];
                    acc2[q][0] = ffma2(pp, vx, acc2[q][0]);
                    acc2[q][1] = ffma2(pp, vy, acc2[q][1]);
                    acc2[q][2] = ffma2(pp, vz, acc2[q][2]);
                    acc2[q][3] = ffma2(pp, vw, acc2[q][3]);
                }
            }
        }
        __syncthreads();
    }

    float va[4][4];
#pragma unroll
    for (int q = 0; q < 2; q++)
#pragma unroll
        for (int dc = 0; dc < 4; dc++)
            unpack2(acc2[q][dc], va[2*q][dc], va[2*q+1][dc]);
    float* obase = g_out4 + ((size_t)(b*NKK + k)*SS)*DD + h*DKK;
#pragma unroll
    for (int r = 0; r < 4; r++){
        *(float4*)(obase + (size_t)(i0 + ii0 + r)*DD + d0) =
            make_float4(va[r][0], va[r][1], va[r][2], va[r][3]);
    }
}

// ---------------- launch ----------------
extern "C" void kernel_launch(void* const* d_in, const int* in_sizes, int n_in,
                              void* d_out, int out_size){
    (void)in_sizes; (void)n_in; (void)out_size;
    const float* q_emb = (const float*)d_in[0];
    const float* s_emb = (const float*)d_in[1];
    const float* Wq1 = (const float*)d_in[5];
    const float* bq1 = (const float*)d_in[6];
    const float* Wv1 = (const float*)d_in[7];
    const float* bv1 = (const float*)d_in[8];
    const float* Wo1 = (const float*)d_in[9];
    const float* bo1 = (const float*)d_in[10];
    const float* gam1= (const float*)d_in[11];
    const float* ln1g= (const float*)d_in[12];
    const float* ln1b= (const float*)d_in[13];
    const float* Wq4 = (const float*)d_in[14];
    const float* bq4 = (const float*)d_in[15];
    const float* Wk4 = (const float*)d_in[16];
    const float* bk4 = (const float*)d_in[17];
    const float* Wv4 = (const float*)d_in[18];
    const float* bv4 = (const float*)d_in[19];
    const float* Wo4 = (const float*)d_in[20];
    const float* bo4 = (const float*)d_in[21];
    const float* gam4= (const float*)d_in[22];
    const float* ln4g= (const float*)d_in[23];
    const float* ln4b= (const float*)d_in[24];
    const float* knowp=(const float*)d_in[25];

    float* out  = (float*)d_out;
    float* z_out = out;                       // [B,S,NK*D]
    float* q_out = out + Z_ELEMS;             // [B,H,S,S]
    float* k_out = out + Z_ELEMS + Q_ELEMS;   // [B,H,S,NK,S]

    transpose_w_kernel<<<1792, 256>>>(Wq1, Wv1, Wo1, Wq4, Wk4, Wv4, Wo4);
    // block-4-independent precompute first
    proj2_kernel<<<dim3(32,4), 256>>>(q_emb, bk4, 4, 2, 0);   // k4 (+T)
    knowproj2_kernel<<<16, 256>>>(knowp, bq4);
    r4pre_kernel<<<256, 256>>>();
    // block 1
    proj2_kernel<<<dim3(32,4), 256>>>(q_emb, bq1, 0, 0, 0);   // q1 (+T); k1 == q1
    proj2_kernel<<<dim3(32,4), 256>>>(s_emb, bv1, 1, 1, 0);   // v1
    attn1_kernel<<<dim3(SS, HH, BB), 256>>>(gam1, q_out);
    epi2_kernel<2><<<32, 256>>>(q_emb, ln1g, ln1b, 2, bo1, 0, nullptr);   // -> g_p
    // block 4
    proj2_kernel<<<dim3(32,4), 256>>>(nullptr, bv4, 5, 3, 1); // v4 from g_p
    attn4_kernel<<<dim3(4, NKK, BB*HH), 256>>>(gam4, k_out);
    epi2_kernel<4><<<256, 256>>>(knowp, ln4g, ln4b, 6, bo4, 1, z_out);    // -> z
}